// round 2
// baseline (speedup 1.0000x reference)
#include <cuda_runtime.h>
#include <math.h>

#define NN 50000
#define HD 128
#define OD 256
#define NE 800000
#define LN_EPS 1e-5f

// ---------------- scratch (static device globals; no allocation) ----------------
__device__ float g_hA[NN * HD];
__device__ float g_hB[NN * HD];
__device__ float g_f [NN * HD];
__device__ float g_agg[NN * HD];
__device__ float g_yA [NN * OD];
__device__ float g_yagg[NN * OD];
__device__ float g_ex[NE];
__device__ float g_m [NN];
__device__ float g_den[NN];
__device__ int   g_flagIsInt;

// ---------------- helpers ----------------
__device__ __forceinline__ void atomicMaxF(float* addr, float v) {
    if (v >= 0.f) atomicMax((int*)addr, __float_as_int(v));
    else          atomicMin((unsigned int*)addr, __float_as_uint(v));
}

__device__ __forceinline__ float lrelu02(float x) {
    return x >= 0.f ? x : 0.2f * x;
}

// ---------------- kernels ----------------

// Detect flag buffer layout: int32 (bytes 1..3 of each word are 0) vs uint8.
__global__ void k_detect_flag(const unsigned char* __restrict__ flag) {
    __shared__ int cnt;
    if (threadIdx.x == 0) cnt = 0;
    __syncthreads();
    int local = 0;
    for (int i = threadIdx.x; i < 4000; i += 256)
        if ((i & 3) != 0 && flag[i] != 0) local = 1;
    if (local) atomicOr(&cnt, 1);
    __syncthreads();
    if (threadIdx.x == 0) g_flagIsInt = (cnt == 0) ? 1 : 0;
}

// EmbeddingBag(sum, per_sample_weights) + bias + relu. One block (128 thr) per node.
__global__ void k_embed(const int* __restrict__ idx, const int* __restrict__ offs,
                        const float* __restrict__ wts, const float* __restrict__ table,
                        const float* __restrict__ bias, float* __restrict__ out) {
    int n = blockIdx.x;
    int t = threadIdx.x;
    int s = offs[n], e = offs[n + 1];
    float acc = 0.f;
    for (int j = s; j < e; ++j)
        acc = fmaf(table[(size_t)idx[j] * HD + t], wts[j], acc);
    out[(size_t)n * HD + t] = fmaxf(acc + bias[t], 0.f);
}

// C[n,OUT] = X[n,128] @ W[128,OUT] + B. 64x64 tile, 256 threads.
__global__ void k_gemm_bias(const float* __restrict__ X, const float* __restrict__ W,
                            const float* __restrict__ B, float* __restrict__ C,
                            int n, int OUT) {
    __shared__ float xs[64][68];
    __shared__ float ws[64][64];
    int row0 = blockIdx.x * 64, col0 = blockIdx.y * 64;
    int tid = threadIdx.x;
    int tx = tid & 15, ty = tid >> 4;
    float acc[4][4] = {};
    for (int kb = 0; kb < 128; kb += 64) {
        for (int i = tid; i < 64 * 64; i += 256) {
            int k = i & 63, r = i >> 6;
            int row = row0 + r;
            xs[k][r] = (row < n) ? X[(size_t)row * 128 + kb + k] : 0.f;
        }
        for (int i = tid; i < 64 * 64; i += 256) {
            int c = i & 63, k = i >> 6;
            ws[k][c] = W[(size_t)(kb + k) * OUT + col0 + c];
        }
        __syncthreads();
#pragma unroll
        for (int k = 0; k < 64; ++k) {
            float4 a = *(const float4*)&xs[k][ty * 4];
            float4 w = *(const float4*)&ws[k][tx * 4];
            acc[0][0] += a.x * w.x; acc[0][1] += a.x * w.y; acc[0][2] += a.x * w.z; acc[0][3] += a.x * w.w;
            acc[1][0] += a.y * w.x; acc[1][1] += a.y * w.y; acc[1][2] += a.y * w.z; acc[1][3] += a.y * w.w;
            acc[2][0] += a.z * w.x; acc[2][1] += a.z * w.y; acc[2][2] += a.z * w.z; acc[2][3] += a.z * w.w;
            acc[3][0] += a.w * w.x; acc[3][1] += a.w * w.y; acc[3][2] += a.w * w.z; acc[3][3] += a.w * w.w;
        }
        __syncthreads();
    }
#pragma unroll
    for (int r = 0; r < 4; ++r) {
        int row = row0 + ty * 4 + r;
        if (row < n) {
#pragma unroll
            for (int c = 0; c < 4; ++c)
                C[(size_t)row * OUT + col0 + tx * 4 + c] = acc[r][c] + B[col0 + tx * 4 + c];
        }
    }
}

// LayerNorm(128) + relu, one warp per row.
__global__ void k_ln_relu(const float* __restrict__ in, float* __restrict__ out,
                          const float* __restrict__ g, const float* __restrict__ b) {
    int row  = blockIdx.x * 8 + (threadIdx.x >> 5);
    int lane = threadIdx.x & 31;
    float4 v = *(const float4*)&in[(size_t)row * HD + lane * 4];
    float s = v.x + v.y + v.z + v.w;
#pragma unroll
    for (int o = 16; o; o >>= 1) s += __shfl_xor_sync(0xffffffffu, s, o);
    float mu = s * (1.f / 128.f);
    float dx = v.x - mu, dy = v.y - mu, dz = v.z - mu, dw = v.w - mu;
    float q = dx * dx + dy * dy + dz * dz + dw * dw;
#pragma unroll
    for (int o = 16; o; o >>= 1) q += __shfl_xor_sync(0xffffffffu, q, o);
    float rs = rsqrtf(q * (1.f / 128.f) + LN_EPS);
    float4 gg = *(const float4*)&g[lane * 4];
    float4 bb = *(const float4*)&b[lane * 4];
    float4 r;
    r.x = fmaxf(dx * rs * gg.x + bb.x, 0.f);
    r.y = fmaxf(dy * rs * gg.y + bb.y, 0.f);
    r.z = fmaxf(dz * rs * gg.z + bb.z, 0.f);
    r.w = fmaxf(dw * rs * gg.w + bb.w, 0.f);
    *(float4*)&out[(size_t)row * HD + lane * 4] = r;
}

__global__ void k_init_md(float* __restrict__ m, float* __restrict__ den) {
    int i = blockIdx.x * 256 + threadIdx.x;
    if (i < NN) { m[i] = __int_as_float(0xff800000); den[i] = 0.f; }
}

// per-edge GAT score + dst-max. Warp/edge.
__global__ void k_edge_score(const float* __restrict__ f, const int* __restrict__ src,
                             const int* __restrict__ dst, const float* __restrict__ attn,
                             float* __restrict__ sc, float* __restrict__ m) {
    int e = blockIdx.x * 8 + (threadIdx.x >> 5);
    int lane = threadIdx.x & 31;
    int u = src[e], v = dst[e];
    float4 fu = *(const float4*)&f[(size_t)u * HD + lane * 4];
    float4 fv = *(const float4*)&f[(size_t)v * HD + lane * 4];
    float4 at = *(const float4*)&attn[lane * 4];
    float acc = lrelu02(fu.x + fv.x) * at.x
              + lrelu02(fu.y + fv.y) * at.y
              + lrelu02(fu.z + fv.z) * at.z
              + lrelu02(fu.w + fv.w) * at.w;
#pragma unroll
    for (int o = 16; o; o >>= 1) acc += __shfl_xor_sync(0xffffffffu, acc, o);
    if (lane == 0) {
        sc[e] = acc;
        atomicMaxF(&m[v], acc);
    }
}

// exp(s - max[dst]) and denominator accumulation.
__global__ void k_edge_exp(float* __restrict__ sc, const int* __restrict__ dst,
                           const float* __restrict__ m, float* __restrict__ den) {
    int e = blockIdx.x * 256 + threadIdx.x;
    if (e < NE) {
        int v = dst[e];
        float ex = expf(sc[e] - m[v]);
        sc[e] = ex;
        atomicAdd(&den[v], ex);
    }
}

// fused feature + label aggregation. One 128-thread block per edge.
__global__ void k_edge_agg(const float* __restrict__ f, const float* __restrict__ yin,
                           const int* __restrict__ src, const int* __restrict__ dst,
                           const float* __restrict__ ex, const float* __restrict__ den,
                           float* __restrict__ agg, float* __restrict__ yagg) {
    int e = blockIdx.x;
    int t = threadIdx.x;
    int u = src[e], v = dst[e];
    float a = ex[e] / den[v];
    atomicAdd(&agg [(size_t)v * HD + t],        f  [(size_t)u * HD + t]        * a);
    atomicAdd(&yagg[(size_t)v * OD + t],        yin[(size_t)u * OD + t]        * a);
    atomicAdd(&yagg[(size_t)v * OD + HD + t],   yin[(size_t)u * OD + HD + t]   * a);
}

// h_new = elu(agg_p + agg_s + 2*x)
__global__ void k_fin_h(const float* __restrict__ agg, const float* __restrict__ x,
                        float* __restrict__ out) {
    int i = blockIdx.x * 256 + threadIdx.x;
    if (i < NN * HD) {
        float v = agg[i] + 2.f * x[i];
        out[i] = v > 0.f ? v : expm1f(v);
    }
}

// yh = flag ? yin : yagg / max(||yagg||_2, 1e-12). Warp/row.
__global__ void k_fin_y(const float* __restrict__ yagg, const float* __restrict__ yin,
                        const void* __restrict__ flag, float* __restrict__ out) {
    int row  = blockIdx.x * 8 + (threadIdx.x >> 5);
    int lane = threadIdx.x & 31;
    size_t base = (size_t)row * OD + lane * 4;
    float4 a = *(const float4*)&yagg[base];
    float4 c = *(const float4*)&yagg[base + 128];
    float q = a.x * a.x + a.y * a.y + a.z * a.z + a.w * a.w
            + c.x * c.x + c.y * c.y + c.z * c.z + c.w * c.w;
#pragma unroll
    for (int o = 16; o; o >>= 1) q += __shfl_xor_sync(0xffffffffu, q, o);
    float inv = 1.f / fmaxf(sqrtf(q), 1e-12f);
    bool fl;
    if (g_flagIsInt) fl = ((const int*)flag)[row] != 0;
    else             fl = ((const unsigned char*)flag)[row] != 0;
    float4 r0, r1;
    if (fl) {
        r0 = *(const float4*)&yin[base];
        r1 = *(const float4*)&yin[base + 128];
    } else {
        r0 = make_float4(a.x * inv, a.y * inv, a.z * inv, a.w * inv);
        r1 = make_float4(c.x * inv, c.y * inv, c.z * inv, c.w * inv);
    }
    *(float4*)&out[base]       = r0;
    *(float4*)&out[base + 128] = r1;
}

// ---------------- host orchestration ----------------
static void run_prop(const float* x, const float* yin,
                     const float* W, const float* b, const float* attn,
                     const int* srcp, const int* dstp,
                     const int* srcs, const int* dsts,
                     const void* flag,
                     float* f, float* agg, float* yagg, float* ex, float* m, float* den,
                     float* hout, float* yout) {
    dim3 g128((NN + 63) / 64, 2);
    k_gemm_bias<<<g128, 256>>>(x, W, b, f, NN, 128);
    cudaMemsetAsync(agg,  0, sizeof(float) * (size_t)NN * HD);
    cudaMemsetAsync(yagg, 0, sizeof(float) * (size_t)NN * OD);
    const int* sarr[2] = {srcp, srcs};
    const int* darr[2] = {dstp, dsts};
    for (int r = 0; r < 2; ++r) {
        k_init_md<<<(NN + 255) / 256, 256>>>(m, den);
        k_edge_score<<<NE / 8, 256>>>(f, sarr[r], darr[r], attn, ex, m);
        k_edge_exp<<<NE / 256, 256>>>(ex, darr[r], m, den);
        k_edge_agg<<<NE, 128>>>(f, yin, sarr[r], darr[r], ex, den, agg, yagg);
    }
    k_fin_h<<<(NN * HD + 255) / 256, 256>>>(agg, x, hout);
    k_fin_y<<<NN / 8, 256>>>(yagg, yin, flag, yout);
}

extern "C" void kernel_launch(void* const* d_in, const int* in_sizes, int n_in,
                              void* d_out, int out_size) {
    const int*   emb_indices = (const int*)  d_in[0];
    const int*   emb_offsets = (const int*)  d_in[1];
    const float* emb_weights = (const float*)d_in[2];
    const float* y           = (const float*)d_in[3];
    const void*  flag        = d_in[4];
    const int* src_p1 = (const int*)d_in[5];
    const int* dst_p1 = (const int*)d_in[6];
    const int* src_s1 = (const int*)d_in[7];
    const int* dst_s1 = (const int*)d_in[8];
    const int* src_p2 = (const int*)d_in[9];
    const int* dst_p2 = (const int*)d_in[10];
    const int* src_s2 = (const int*)d_in[11];
    const int* dst_s2 = (const int*)d_in[12];
    const float* embed_W = (const float*)d_in[13];
    const float* embed_b = (const float*)d_in[14];
    const float* mlp_W1  = (const float*)d_in[15];
    const float* mlp_b1  = (const float*)d_in[16];
    const float* ln1_g   = (const float*)d_in[17];
    const float* ln1_b   = (const float*)d_in[18];
    const float* mlp_W2  = (const float*)d_in[19];
    const float* mlp_b2  = (const float*)d_in[20];
    const float* ln2_g   = (const float*)d_in[21];
    const float* ln2_b   = (const float*)d_in[22];
    const float* Wsrc1   = (const float*)d_in[23];
    const float* bsrc1   = (const float*)d_in[24];
    const float* attn1   = (const float*)d_in[25];
    const float* Wsrc2   = (const float*)d_in[26];
    const float* bsrc2   = (const float*)d_in[27];
    const float* attn2   = (const float*)d_in[28];
    const float* out_W   = (const float*)d_in[29];
    const float* out_b   = (const float*)d_in[30];

    float *hA, *hB, *f, *agg, *yA, *yagg, *ex, *m, *den;
    cudaGetSymbolAddress((void**)&hA,   g_hA);
    cudaGetSymbolAddress((void**)&hB,   g_hB);
    cudaGetSymbolAddress((void**)&f,    g_f);
    cudaGetSymbolAddress((void**)&agg,  g_agg);
    cudaGetSymbolAddress((void**)&yA,   g_yA);
    cudaGetSymbolAddress((void**)&yagg, g_yagg);
    cudaGetSymbolAddress((void**)&ex,   g_ex);
    cudaGetSymbolAddress((void**)&m,    g_m);
    cudaGetSymbolAddress((void**)&den,  g_den);

    float* logits = (float*)d_out;
    float* yh_out = (float*)d_out + (size_t)NN * OD;

    k_detect_flag<<<1, 256>>>((const unsigned char*)flag);

    // 1) EmbeddingBag + bias + relu
    k_embed<<<NN, 128>>>(emb_indices, emb_offsets, emb_weights, embed_W, embed_b, hA);

    // 2) MLP: (Linear -> LN -> ReLU) x 2
    dim3 g128((NN + 63) / 64, 2);
    k_gemm_bias<<<g128, 256>>>(hA, mlp_W1, mlp_b1, f, NN, 128);
    k_ln_relu<<<NN / 8, 256>>>(f, hB, ln1_g, ln1_b);
    k_gemm_bias<<<g128, 256>>>(hB, mlp_W2, mlp_b2, f, NN, 128);
    k_ln_relu<<<NN / 8, 256>>>(f, hA, ln2_g, ln2_b);

    // 3) prop 1: x = hA -> hB, y -> yA
    run_prop(hA, y, Wsrc1, bsrc1, attn1, src_p1, dst_p1, src_s1, dst_s1, flag,
             f, agg, yagg, ex, m, den, hB, yA);

    // 4) prop 2: x = hB -> hA, yA -> yh_out
    run_prop(hB, yA, Wsrc2, bsrc2, attn2, src_p2, dst_p2, src_s2, dst_s2, flag,
             f, agg, yagg, ex, m, den, hA, yh_out);

    // 5) logits = h @ out_W + out_b
    dim3 g256((NN + 63) / 64, 4);
    k_gemm_bias<<<g256, 256>>>(hA, out_W, out_b, logits, NN, 256);
}

// round 3
// speedup vs baseline: 1.3986x; 1.3986x over previous
#include <cuda_runtime.h>
#include <math.h>

#define NN 50000
#define HD 128
#define OD 256
#define NE 800000
#define LN_EPS 1e-5f

// ---------------- scratch (static device globals; no allocation) ----------------
__device__ float g_hA[NN * HD];
__device__ float g_hB[NN * HD];
__device__ float g_f [NN * HD];
__device__ float g_agg[NN * HD];
__device__ float g_yA [NN * OD];
__device__ float g_yagg[NN * OD];
__device__ float g_ex[2 * NE];
__device__ float g_m [2 * NN];
__device__ float g_den[2 * NN];
__device__ int   g_flagIsInt;

// ---------------- helpers ----------------
__device__ __forceinline__ void atomicMaxF(float* addr, float v) {
    if (v >= 0.f) atomicMax((int*)addr, __float_as_int(v));
    else          atomicMin((unsigned int*)addr, __float_as_uint(v));
}

__device__ __forceinline__ float lrelu02(float x) {
    return x >= 0.f ? x : 0.2f * x;
}

__device__ __forceinline__ void redAddV4(float* addr, float4 v) {
    asm volatile("red.global.add.v4.f32 [%0], {%1,%2,%3,%4};"
                 :: "l"(addr), "f"(v.x), "f"(v.y), "f"(v.z), "f"(v.w) : "memory");
}

// ---------------- kernels ----------------

// Detect flag buffer layout: int32 (bytes 1..3 of each word are 0) vs uint8.
__global__ void k_detect_flag(const unsigned char* __restrict__ flag) {
    __shared__ int cnt;
    if (threadIdx.x == 0) cnt = 0;
    __syncthreads();
    int local = 0;
    for (int i = threadIdx.x; i < 4000; i += 256)
        if ((i & 3) != 0 && flag[i] != 0) local = 1;
    if (local) atomicOr(&cnt, 1);
    __syncthreads();
    if (threadIdx.x == 0) g_flagIsInt = (cnt == 0) ? 1 : 0;
}

// EmbeddingBag(sum, per_sample_weights) + bias + relu. Warp per node, float4 per lane.
__global__ void k_embed(const int* __restrict__ idx, const int* __restrict__ offs,
                        const float* __restrict__ wts, const float* __restrict__ table,
                        const float* __restrict__ bias, float* __restrict__ out) {
    int n = blockIdx.x * 8 + (threadIdx.x >> 5);
    if (n >= NN) return;
    int lane = threadIdx.x & 31;
    int s = offs[n], e = offs[n + 1];
    float4 acc = make_float4(0.f, 0.f, 0.f, 0.f);
    for (int base = s; base < e; base += 32) {
        int j = base + lane;
        int id = (j < e) ? idx[j] : 0;
        float w = (j < e) ? wts[j] : 0.f;
        int cnt = min(32, e - base);
        for (int t = 0; t < cnt; ++t) {
            int   uj = __shfl_sync(0xffffffffu, id, t);
            float wj = __shfl_sync(0xffffffffu, w,  t);
            float4 tv = *(const float4*)&table[(size_t)uj * HD + lane * 4];
            acc.x = fmaf(tv.x, wj, acc.x);
            acc.y = fmaf(tv.y, wj, acc.y);
            acc.z = fmaf(tv.z, wj, acc.z);
            acc.w = fmaf(tv.w, wj, acc.w);
        }
    }
    float4 b4 = *(const float4*)&bias[lane * 4];
    float4 r;
    r.x = fmaxf(acc.x + b4.x, 0.f);
    r.y = fmaxf(acc.y + b4.y, 0.f);
    r.z = fmaxf(acc.z + b4.z, 0.f);
    r.w = fmaxf(acc.w + b4.w, 0.f);
    *(float4*)&out[(size_t)n * HD + lane * 4] = r;
}

// C[n,OUT] = X[n,128] @ W[128,OUT] + B. 64x64 tile, 256 threads.
__global__ void k_gemm_bias(const float* __restrict__ X, const float* __restrict__ W,
                            const float* __restrict__ B, float* __restrict__ C,
                            int n, int OUT) {
    __shared__ float xs[64][68];
    __shared__ float ws[64][64];
    int row0 = blockIdx.x * 64, col0 = blockIdx.y * 64;
    int tid = threadIdx.x;
    int tx = tid & 15, ty = tid >> 4;
    float acc[4][4] = {};
    for (int kb = 0; kb < 128; kb += 64) {
        for (int i = tid; i < 64 * 64; i += 256) {
            int k = i & 63, r = i >> 6;
            int row = row0 + r;
            xs[k][r] = (row < n) ? X[(size_t)row * 128 + kb + k] : 0.f;
        }
        for (int i = tid; i < 64 * 64; i += 256) {
            int c = i & 63, k = i >> 6;
            ws[k][c] = W[(size_t)(kb + k) * OUT + col0 + c];
        }
        __syncthreads();
#pragma unroll
        for (int k = 0; k < 64; ++k) {
            float4 a = *(const float4*)&xs[k][ty * 4];
            float4 w = *(const float4*)&ws[k][tx * 4];
            acc[0][0] += a.x * w.x; acc[0][1] += a.x * w.y; acc[0][2] += a.x * w.z; acc[0][3] += a.x * w.w;
            acc[1][0] += a.y * w.x; acc[1][1] += a.y * w.y; acc[1][2] += a.y * w.z; acc[1][3] += a.y * w.w;
            acc[2][0] += a.z * w.x; acc[2][1] += a.z * w.y; acc[2][2] += a.z * w.z; acc[2][3] += a.z * w.w;
            acc[3][0] += a.w * w.x; acc[3][1] += a.w * w.y; acc[3][2] += a.w * w.z; acc[3][3] += a.w * w.w;
        }
        __syncthreads();
    }
#pragma unroll
    for (int r = 0; r < 4; ++r) {
        int row = row0 + ty * 4 + r;
        if (row < n) {
#pragma unroll
            for (int c = 0; c < 4; ++c)
                C[(size_t)row * OUT + col0 + tx * 4 + c] = acc[r][c] + B[col0 + tx * 4 + c];
        }
    }
}

// LayerNorm(128) + relu, one warp per row.
__global__ void k_ln_relu(const float* __restrict__ in, float* __restrict__ out,
                          const float* __restrict__ g, const float* __restrict__ b) {
    int row  = blockIdx.x * 8 + (threadIdx.x >> 5);
    int lane = threadIdx.x & 31;
    float4 v = *(const float4*)&in[(size_t)row * HD + lane * 4];
    float s = v.x + v.y + v.z + v.w;
#pragma unroll
    for (int o = 16; o; o >>= 1) s += __shfl_xor_sync(0xffffffffu, s, o);
    float mu = s * (1.f / 128.f);
    float dx = v.x - mu, dy = v.y - mu, dz = v.z - mu, dw = v.w - mu;
    float q = dx * dx + dy * dy + dz * dz + dw * dw;
#pragma unroll
    for (int o = 16; o; o >>= 1) q += __shfl_xor_sync(0xffffffffu, q, o);
    float rs = rsqrtf(q * (1.f / 128.f) + LN_EPS);
    float4 gg = *(const float4*)&g[lane * 4];
    float4 bb = *(const float4*)&b[lane * 4];
    float4 r;
    r.x = fmaxf(dx * rs * gg.x + bb.x, 0.f);
    r.y = fmaxf(dy * rs * gg.y + bb.y, 0.f);
    r.z = fmaxf(dz * rs * gg.z + bb.z, 0.f);
    r.w = fmaxf(dw * rs * gg.w + bb.w, 0.f);
    *(float4*)&out[(size_t)row * HD + lane * 4] = r;
}

// init m = -inf, den = 0 for BOTH relations (2*NN each)
__global__ void k_init_md(float* __restrict__ m, float* __restrict__ den) {
    int i = blockIdx.x * 256 + threadIdx.x;
    if (i < 2 * NN) { m[i] = __int_as_float(0xff800000); den[i] = 0.f; }
}

// per-edge GAT score + dst-max, BOTH relations in one grid. Warp/edge.
__global__ void k_edge_score2(const float* __restrict__ f,
                              const int* __restrict__ srcp, const int* __restrict__ dstp,
                              const int* __restrict__ srcs, const int* __restrict__ dsts,
                              const float* __restrict__ attn,
                              float* __restrict__ sc, float* __restrict__ m) {
    int eg = blockIdx.x * 8 + (threadIdx.x >> 5);
    int lane = threadIdx.x & 31;
    int rel = eg >= NE;
    int e = eg - rel * NE;
    const int* src = rel ? srcs : srcp;
    const int* dst = rel ? dsts : dstp;
    int u = src[e], v = dst[e];
    float4 fu = *(const float4*)&f[(size_t)u * HD + lane * 4];
    float4 fv = *(const float4*)&f[(size_t)v * HD + lane * 4];
    float4 at = *(const float4*)&attn[lane * 4];
    float acc = lrelu02(fu.x + fv.x) * at.x
              + lrelu02(fu.y + fv.y) * at.y
              + lrelu02(fu.z + fv.z) * at.z
              + lrelu02(fu.w + fv.w) * at.w;
#pragma unroll
    for (int o = 16; o; o >>= 1) acc += __shfl_xor_sync(0xffffffffu, acc, o);
    if (lane == 0) {
        sc[eg] = acc;
        atomicMaxF(&m[rel * NN + v], acc);
    }
}

// exp(s - max[dst]) and denominator accumulation, both relations.
__global__ void k_edge_exp2(float* __restrict__ sc,
                            const int* __restrict__ dstp, const int* __restrict__ dsts,
                            const float* __restrict__ m, float* __restrict__ den) {
    int eg = blockIdx.x * 256 + threadIdx.x;
    if (eg < 2 * NE) {
        int rel = eg >= NE;
        int e = eg - rel * NE;
        int v = (rel ? dsts : dstp)[e];
        float ex = expf(sc[eg] - m[rel * NN + v]);
        sc[eg] = ex;
        atomicAdd(&den[rel * NN + v], ex);
    }
}

// fused feature + label aggregation, both relations. Warp per edge, v4 reductions.
__global__ void k_edge_agg2(const float* __restrict__ f, const float* __restrict__ yin,
                            const int* __restrict__ srcp, const int* __restrict__ dstp,
                            const int* __restrict__ srcs, const int* __restrict__ dsts,
                            const float* __restrict__ ex, const float* __restrict__ den,
                            float* __restrict__ agg, float* __restrict__ yagg) {
    int eg = blockIdx.x * 8 + (threadIdx.x >> 5);
    int lane = threadIdx.x & 31;
    int rel = eg >= NE;
    int e = eg - rel * NE;
    const int* src = rel ? srcs : srcp;
    const int* dst = rel ? dsts : dstp;
    int u = src[e], v = dst[e];
    float a = ex[eg] / den[rel * NN + v];

    float4 fv = *(const float4*)&f[(size_t)u * HD + lane * 4];
    fv.x *= a; fv.y *= a; fv.z *= a; fv.w *= a;
    redAddV4(&agg[(size_t)v * HD + lane * 4], fv);

    float4 y0 = *(const float4*)&yin[(size_t)u * OD + lane * 4];
    float4 y1 = *(const float4*)&yin[(size_t)u * OD + 128 + lane * 4];
    y0.x *= a; y0.y *= a; y0.z *= a; y0.w *= a;
    y1.x *= a; y1.y *= a; y1.z *= a; y1.w *= a;
    redAddV4(&yagg[(size_t)v * OD + lane * 4],       y0);
    redAddV4(&yagg[(size_t)v * OD + 128 + lane * 4], y1);
}

// h_new = elu(agg_p + agg_s + 2*x)
__global__ void k_fin_h(const float* __restrict__ agg, const float* __restrict__ x,
                        float* __restrict__ out) {
    int i = blockIdx.x * 256 + threadIdx.x;
    if (i < NN * HD) {
        float v = agg[i] + 2.f * x[i];
        out[i] = v > 0.f ? v : expm1f(v);
    }
}

// yh = flag ? yin : yagg / max(||yagg||_2, 1e-12). Warp/row.
__global__ void k_fin_y(const float* __restrict__ yagg, const float* __restrict__ yin,
                        const void* __restrict__ flag, float* __restrict__ out) {
    int row  = blockIdx.x * 8 + (threadIdx.x >> 5);
    int lane = threadIdx.x & 31;
    size_t base = (size_t)row * OD + lane * 4;
    float4 a = *(const float4*)&yagg[base];
    float4 c = *(const float4*)&yagg[base + 128];
    float q = a.x * a.x + a.y * a.y + a.z * a.z + a.w * a.w
            + c.x * c.x + c.y * c.y + c.z * c.z + c.w * c.w;
#pragma unroll
    for (int o = 16; o; o >>= 1) q += __shfl_xor_sync(0xffffffffu, q, o);
    float inv = 1.f / fmaxf(sqrtf(q), 1e-12f);
    bool fl;
    if (g_flagIsInt) fl = ((const int*)flag)[row] != 0;
    else             fl = ((const unsigned char*)flag)[row] != 0;
    float4 r0, r1;
    if (fl) {
        r0 = *(const float4*)&yin[base];
        r1 = *(const float4*)&yin[base + 128];
    } else {
        r0 = make_float4(a.x * inv, a.y * inv, a.z * inv, a.w * inv);
        r1 = make_float4(c.x * inv, c.y * inv, c.z * inv, c.w * inv);
    }
    *(float4*)&out[base]       = r0;
    *(float4*)&out[base + 128] = r1;
}

// ---------------- host orchestration ----------------
static void run_prop(const float* x, const float* yin,
                     const float* W, const float* b, const float* attn,
                     const int* srcp, const int* dstp,
                     const int* srcs, const int* dsts,
                     const void* flag,
                     float* f, float* agg, float* yagg, float* ex, float* m, float* den,
                     float* hout, float* yout) {
    dim3 g128((NN + 63) / 64, 2);
    k_gemm_bias<<<g128, 256>>>(x, W, b, f, NN, 128);
    cudaMemsetAsync(agg,  0, sizeof(float) * (size_t)NN * HD);
    cudaMemsetAsync(yagg, 0, sizeof(float) * (size_t)NN * OD);
    k_init_md<<<(2 * NN + 255) / 256, 256>>>(m, den);
    k_edge_score2<<<2 * NE / 8, 256>>>(f, srcp, dstp, srcs, dsts, attn, ex, m);
    k_edge_exp2<<<2 * NE / 256, 256>>>(ex, dstp, dsts, m, den);
    k_edge_agg2<<<2 * NE / 8, 256>>>(f, yin, srcp, dstp, srcs, dsts, ex, den, agg, yagg);
    k_fin_h<<<(NN * HD + 255) / 256, 256>>>(agg, x, hout);
    k_fin_y<<<NN / 8, 256>>>(yagg, yin, flag, yout);
}

extern "C" void kernel_launch(void* const* d_in, const int* in_sizes, int n_in,
                              void* d_out, int out_size) {
    const int*   emb_indices = (const int*)  d_in[0];
    const int*   emb_offsets = (const int*)  d_in[1];
    const float* emb_weights = (const float*)d_in[2];
    const float* y           = (const float*)d_in[3];
    const void*  flag        = d_in[4];
    const int* src_p1 = (const int*)d_in[5];
    const int* dst_p1 = (const int*)d_in[6];
    const int* src_s1 = (const int*)d_in[7];
    const int* dst_s1 = (const int*)d_in[8];
    const int* src_p2 = (const int*)d_in[9];
    const int* dst_p2 = (const int*)d_in[10];
    const int* src_s2 = (const int*)d_in[11];
    const int* dst_s2 = (const int*)d_in[12];
    const float* embed_W = (const float*)d_in[13];
    const float* embed_b = (const float*)d_in[14];
    const float* mlp_W1  = (const float*)d_in[15];
    const float* mlp_b1  = (const float*)d_in[16];
    const float* ln1_g   = (const float*)d_in[17];
    const float* ln1_b   = (const float*)d_in[18];
    const float* mlp_W2  = (const float*)d_in[19];
    const float* mlp_b2  = (const float*)d_in[20];
    const float* ln2_g   = (const float*)d_in[21];
    const float* ln2_b   = (const float*)d_in[22];
    const float* Wsrc1   = (const float*)d_in[23];
    const float* bsrc1   = (const float*)d_in[24];
    const float* attn1   = (const float*)d_in[25];
    const float* Wsrc2   = (const float*)d_in[26];
    const float* bsrc2   = (const float*)d_in[27];
    const float* attn2   = (const float*)d_in[28];
    const float* out_W   = (const float*)d_in[29];
    const float* out_b   = (const float*)d_in[30];

    float *hA, *hB, *f, *agg, *yA, *yagg, *ex, *m, *den;
    cudaGetSymbolAddress((void**)&hA,   g_hA);
    cudaGetSymbolAddress((void**)&hB,   g_hB);
    cudaGetSymbolAddress((void**)&f,    g_f);
    cudaGetSymbolAddress((void**)&agg,  g_agg);
    cudaGetSymbolAddress((void**)&yA,   g_yA);
    cudaGetSymbolAddress((void**)&yagg, g_yagg);
    cudaGetSymbolAddress((void**)&ex,   g_ex);
    cudaGetSymbolAddress((void**)&m,    g_m);
    cudaGetSymbolAddress((void**)&den,  g_den);

    float* logits = (float*)d_out;
    float* yh_out = (float*)d_out + (size_t)NN * OD;

    k_detect_flag<<<1, 256>>>((const unsigned char*)flag);

    // 1) EmbeddingBag + bias + relu
    k_embed<<<(NN + 7) / 8, 256>>>(emb_indices, emb_offsets, emb_weights, embed_W, embed_b, hA);

    // 2) MLP: (Linear -> LN -> ReLU) x 2
    dim3 g128((NN + 63) / 64, 2);
    k_gemm_bias<<<g128, 256>>>(hA, mlp_W1, mlp_b1, f, NN, 128);
    k_ln_relu<<<NN / 8, 256>>>(f, hB, ln1_g, ln1_b);
    k_gemm_bias<<<g128, 256>>>(hB, mlp_W2, mlp_b2, f, NN, 128);
    k_ln_relu<<<NN / 8, 256>>>(f, hA, ln2_g, ln2_b);

    // 3) prop 1: x = hA -> hB, y -> yA
    run_prop(hA, y, Wsrc1, bsrc1, attn1, src_p1, dst_p1, src_s1, dst_s1, flag,
             f, agg, yagg, ex, m, den, hB, yA);

    // 4) prop 2: x = hB -> hA, yA -> yh_out
    run_prop(hB, yA, Wsrc2, bsrc2, attn2, src_p2, dst_p2, src_s2, dst_s2, flag,
             f, agg, yagg, ex, m, den, hA, yh_out);

    // 5) logits = h @ out_W + out_b
    dim3 g256((NN + 63) / 64, 4);
    k_gemm_bias<<<g256, 256>>>(hA, out_W, out_b, logits, NN, 256);
}

// round 4
// speedup vs baseline: 2.0960x; 1.4987x over previous
#include <cuda_runtime.h>
#include <math.h>

#define NN 50000
#define HD 128
#define OD 256
#define NE 800000
#define LN_EPS 1e-5f

// ---------------- scratch (static device globals; no allocation) ----------------
__device__ float g_hA[NN * HD];
__device__ float g_hB[NN * HD];
__device__ float g_f [NN * HD];
__device__ float g_yA [NN * OD];
__device__ float g_sc[2 * NE];
__device__ int   g_off [4][NN + 1];
__device__ int   g_ssrc[4][NE];
__device__ int   g_cnt[NN];
__device__ int   g_cur[NN];
__device__ int   g_flagIsInt;

// ---------------- helpers ----------------
__device__ __forceinline__ float lrelu02(float x) {
    return x >= 0.f ? x : 0.2f * x;
}

// ---------------- kernels ----------------

// Detect flag buffer layout: int32 (bytes 1..3 of each word are 0) vs uint8.
__global__ void k_detect_flag(const unsigned char* __restrict__ flag) {
    __shared__ int cnt;
    if (threadIdx.x == 0) cnt = 0;
    __syncthreads();
    int local = 0;
    for (int i = threadIdx.x; i < 4000; i += 256)
        if ((i & 3) != 0 && flag[i] != 0) local = 1;
    if (local) atomicOr(&cnt, 1);
    __syncthreads();
    if (threadIdx.x == 0) g_flagIsInt = (cnt == 0) ? 1 : 0;
}

// -------- counting sort by dst --------
__global__ void k_hist(const int* __restrict__ dst, int* __restrict__ cnt) {
    int e = blockIdx.x * 256 + threadIdx.x;
    if (e < NE) atomicAdd(&cnt[dst[e]], 1);
}

// single-block exclusive scan over NN counts -> offs[NN+1], cur[NN]
__global__ void k_scan(const int* __restrict__ cnt, int* __restrict__ offs,
                       int* __restrict__ cur) {
    __shared__ int part[1024];
    const int CH = (NN + 1023) / 1024;  // 49
    int t = threadIdx.x;
    int lo = t * CH, hi = min(lo + CH, NN);
    int s = 0;
    for (int i = lo; i < hi; ++i) s += cnt[i];
    part[t] = s;
    __syncthreads();
    for (int o = 1; o < 1024; o <<= 1) {
        int v = (t >= o) ? part[t - o] : 0;
        __syncthreads();
        part[t] += v;
        __syncthreads();
    }
    int base = (t == 0) ? 0 : part[t - 1];
    for (int i = lo; i < hi; ++i) {
        offs[i] = base;
        cur[i]  = base;
        base += cnt[i];
    }
    if (t == 1023) offs[NN] = base;
}

__global__ void k_scatter(const int* __restrict__ src, const int* __restrict__ dst,
                          int* __restrict__ cur, int* __restrict__ ssrc) {
    int e = blockIdx.x * 256 + threadIdx.x;
    if (e < NE) {
        int v = dst[e];
        int pos = atomicAdd(&cur[v], 1);
        ssrc[pos] = src[e];
    }
}

// EmbeddingBag(sum, per_sample_weights) + bias + relu. Warp per node.
__global__ void k_embed(const int* __restrict__ idx, const int* __restrict__ offs,
                        const float* __restrict__ wts, const float* __restrict__ table,
                        const float* __restrict__ bias, float* __restrict__ out) {
    int n = blockIdx.x * 8 + (threadIdx.x >> 5);
    if (n >= NN) return;
    int lane = threadIdx.x & 31;
    int s = offs[n], e = offs[n + 1];
    float4 acc = make_float4(0.f, 0.f, 0.f, 0.f);
    for (int base = s; base < e; base += 32) {
        int j = base + lane;
        int id = (j < e) ? idx[j] : 0;
        float w = (j < e) ? wts[j] : 0.f;
        int cnt = min(32, e - base);
        for (int t = 0; t < cnt; ++t) {
            int   uj = __shfl_sync(0xffffffffu, id, t);
            float wj = __shfl_sync(0xffffffffu, w,  t);
            float4 tv = *(const float4*)&table[(size_t)uj * HD + lane * 4];
            acc.x = fmaf(tv.x, wj, acc.x);
            acc.y = fmaf(tv.y, wj, acc.y);
            acc.z = fmaf(tv.z, wj, acc.z);
            acc.w = fmaf(tv.w, wj, acc.w);
        }
    }
    float4 b4 = *(const float4*)&bias[lane * 4];
    float4 r;
    r.x = fmaxf(acc.x + b4.x, 0.f);
    r.y = fmaxf(acc.y + b4.y, 0.f);
    r.z = fmaxf(acc.z + b4.z, 0.f);
    r.w = fmaxf(acc.w + b4.w, 0.f);
    *(float4*)&out[(size_t)n * HD + lane * 4] = r;
}

// C[n,OUT] = X[n,128] @ W[128,OUT] + B. 64x64 tile, 256 threads.
__global__ void k_gemm_bias(const float* __restrict__ X, const float* __restrict__ W,
                            const float* __restrict__ B, float* __restrict__ C,
                            int n, int OUT) {
    __shared__ float xs[64][68];
    __shared__ float ws[64][64];
    int row0 = blockIdx.x * 64, col0 = blockIdx.y * 64;
    int tid = threadIdx.x;
    int tx = tid & 15, ty = tid >> 4;
    float acc[4][4] = {};
    for (int kb = 0; kb < 128; kb += 64) {
        for (int i = tid; i < 64 * 64; i += 256) {
            int k = i & 63, r = i >> 6;
            int row = row0 + r;
            xs[k][r] = (row < n) ? X[(size_t)row * 128 + kb + k] : 0.f;
        }
        for (int i = tid; i < 64 * 64; i += 256) {
            int c = i & 63, k = i >> 6;
            ws[k][c] = W[(size_t)(kb + k) * OUT + col0 + c];
        }
        __syncthreads();
#pragma unroll
        for (int k = 0; k < 64; ++k) {
            float4 a = *(const float4*)&xs[k][ty * 4];
            float4 w = *(const float4*)&ws[k][tx * 4];
            acc[0][0] += a.x * w.x; acc[0][1] += a.x * w.y; acc[0][2] += a.x * w.z; acc[0][3] += a.x * w.w;
            acc[1][0] += a.y * w.x; acc[1][1] += a.y * w.y; acc[1][2] += a.y * w.z; acc[1][3] += a.y * w.w;
            acc[2][0] += a.z * w.x; acc[2][1] += a.z * w.y; acc[2][2] += a.z * w.z; acc[2][3] += a.z * w.w;
            acc[3][0] += a.w * w.x; acc[3][1] += a.w * w.y; acc[3][2] += a.w * w.z; acc[3][3] += a.w * w.w;
        }
        __syncthreads();
    }
#pragma unroll
    for (int r = 0; r < 4; ++r) {
        int row = row0 + ty * 4 + r;
        if (row < n) {
#pragma unroll
            for (int c = 0; c < 4; ++c)
                C[(size_t)row * OUT + col0 + tx * 4 + c] = acc[r][c] + B[col0 + tx * 4 + c];
        }
    }
}

// LayerNorm(128) + relu, one warp per row.
__global__ void k_ln_relu(const float* __restrict__ in, float* __restrict__ out,
                          const float* __restrict__ g, const float* __restrict__ b) {
    int row  = blockIdx.x * 8 + (threadIdx.x >> 5);
    int lane = threadIdx.x & 31;
    float4 v = *(const float4*)&in[(size_t)row * HD + lane * 4];
    float s = v.x + v.y + v.z + v.w;
#pragma unroll
    for (int o = 16; o; o >>= 1) s += __shfl_xor_sync(0xffffffffu, s, o);
    float mu = s * (1.f / 128.f);
    float dx = v.x - mu, dy = v.y - mu, dz = v.z - mu, dw = v.w - mu;
    float q = dx * dx + dy * dy + dz * dz + dw * dw;
#pragma unroll
    for (int o = 16; o; o >>= 1) q += __shfl_xor_sync(0xffffffffu, q, o);
    float rs = rsqrtf(q * (1.f / 128.f) + LN_EPS);
    float4 gg = *(const float4*)&g[lane * 4];
    float4 bb = *(const float4*)&b[lane * 4];
    float4 r;
    r.x = fmaxf(dx * rs * gg.x + bb.x, 0.f);
    r.y = fmaxf(dy * rs * gg.y + bb.y, 0.f);
    r.z = fmaxf(dz * rs * gg.z + bb.z, 0.f);
    r.w = fmaxf(dw * rs * gg.w + bb.w, 0.f);
    *(float4*)&out[(size_t)row * HD + lane * 4] = r;
}

// ---------------- fused per-destination prop kernel ----------------
// Warp per dst node. For both relations: online-softmax GAT attention over the
// node's incoming (CSR-sorted) edges, then register-accumulated feature +
// label aggregation, then elu-residual (h) and normalize/flag (yh) epilogues.
__global__ void k_prop(const float* __restrict__ f, const float* __restrict__ x,
                       const float* __restrict__ yin, const float* __restrict__ attn,
                       const int* __restrict__ offp, const int* __restrict__ sp,
                       const int* __restrict__ offs2, const int* __restrict__ ss,
                       float* __restrict__ scp, float* __restrict__ scs,
                       const void* __restrict__ flag,
                       float* __restrict__ hout, float* __restrict__ yout) {
    int v = blockIdx.x * 8 + (threadIdx.x >> 5);
    if (v >= NN) return;
    int lane = threadIdx.x & 31;

    float4 at = *(const float4*)&attn[lane * 4];
    float4 fv = *(const float4*)&f[(size_t)v * HD + lane * 4];

    float4 accf = make_float4(0.f, 0.f, 0.f, 0.f);
    float4 ay0  = make_float4(0.f, 0.f, 0.f, 0.f);
    float4 ay1  = make_float4(0.f, 0.f, 0.f, 0.f);

#pragma unroll
    for (int rel = 0; rel < 2; ++rel) {
        const int* off  = rel ? offs2 : offp;
        const int* ssrc = rel ? ss    : sp;
        float*     sc   = rel ? scs   : scp;
        int lo = off[v], hi = off[v + 1];

        // pass A: scores + online softmax (max, den)
        float m = -__int_as_float(0x7f800000);  // -inf
        float den = 0.f;
        for (int j = lo; j < hi; ++j) {
            int u = __ldg(&ssrc[j]);
            float4 fu = *(const float4*)&f[(size_t)u * HD + lane * 4];
            float p = lrelu02(fu.x + fv.x) * at.x
                    + lrelu02(fu.y + fv.y) * at.y
                    + lrelu02(fu.z + fv.z) * at.z
                    + lrelu02(fu.w + fv.w) * at.w;
#pragma unroll
            for (int o = 16; o; o >>= 1) p += __shfl_xor_sync(0xffffffffu, p, o);
            sc[j] = p;  // all lanes write identical value
            if (p > m) { den *= expf(m - p); m = p; }
            den += expf(p - m);
        }
        float rden = (den > 0.f) ? 1.f / den : 0.f;

        // pass B: weighted aggregation
        for (int j = lo; j < hi; ++j) {
            int u = __ldg(&ssrc[j]);
            float a = expf(sc[j] - m) * rden;
            float4 fu = *(const float4*)&f[(size_t)u * HD + lane * 4];
            accf.x = fmaf(fu.x, a, accf.x);
            accf.y = fmaf(fu.y, a, accf.y);
            accf.z = fmaf(fu.z, a, accf.z);
            accf.w = fmaf(fu.w, a, accf.w);
            float4 y0 = *(const float4*)&yin[(size_t)u * OD + lane * 4];
            float4 y1 = *(const float4*)&yin[(size_t)u * OD + 128 + lane * 4];
            ay0.x = fmaf(y0.x, a, ay0.x); ay0.y = fmaf(y0.y, a, ay0.y);
            ay0.z = fmaf(y0.z, a, ay0.z); ay0.w = fmaf(y0.w, a, ay0.w);
            ay1.x = fmaf(y1.x, a, ay1.x); ay1.y = fmaf(y1.y, a, ay1.y);
            ay1.z = fmaf(y1.z, a, ay1.z); ay1.w = fmaf(y1.w, a, ay1.w);
        }
    }

    // h epilogue: elu(agg_p + agg_s + 2*x)
    float4 xv = *(const float4*)&x[(size_t)v * HD + lane * 4];
    float4 h;
    h.x = accf.x + 2.f * xv.x; h.x = h.x > 0.f ? h.x : expm1f(h.x);
    h.y = accf.y + 2.f * xv.y; h.y = h.y > 0.f ? h.y : expm1f(h.y);
    h.z = accf.z + 2.f * xv.z; h.z = h.z > 0.f ? h.z : expm1f(h.z);
    h.w = accf.w + 2.f * xv.w; h.w = h.w > 0.f ? h.w : expm1f(h.w);
    *(float4*)&hout[(size_t)v * HD + lane * 4] = h;

    // y epilogue: normalize or copy per flag
    float q = ay0.x * ay0.x + ay0.y * ay0.y + ay0.z * ay0.z + ay0.w * ay0.w
            + ay1.x * ay1.x + ay1.y * ay1.y + ay1.z * ay1.z + ay1.w * ay1.w;
#pragma unroll
    for (int o = 16; o; o >>= 1) q += __shfl_xor_sync(0xffffffffu, q, o);
    float inv = 1.f / fmaxf(sqrtf(q), 1e-12f);
    bool fl;
    if (g_flagIsInt) fl = ((const int*)flag)[v] != 0;
    else             fl = ((const unsigned char*)flag)[v] != 0;
    size_t base = (size_t)v * OD + lane * 4;
    float4 r0, r1;
    if (fl) {
        r0 = *(const float4*)&yin[base];
        r1 = *(const float4*)&yin[base + 128];
    } else {
        r0 = make_float4(ay0.x * inv, ay0.y * inv, ay0.z * inv, ay0.w * inv);
        r1 = make_float4(ay1.x * inv, ay1.y * inv, ay1.z * inv, ay1.w * inv);
    }
    *(float4*)&yout[base]       = r0;
    *(float4*)&yout[base + 128] = r1;
}

// ---------------- host orchestration ----------------
extern "C" void kernel_launch(void* const* d_in, const int* in_sizes, int n_in,
                              void* d_out, int out_size) {
    const int*   emb_indices = (const int*)  d_in[0];
    const int*   emb_offsets = (const int*)  d_in[1];
    const float* emb_weights = (const float*)d_in[2];
    const float* y           = (const float*)d_in[3];
    const void*  flag        = d_in[4];
    const int* src_p1 = (const int*)d_in[5];
    const int* dst_p1 = (const int*)d_in[6];
    const int* src_s1 = (const int*)d_in[7];
    const int* dst_s1 = (const int*)d_in[8];
    const int* src_p2 = (const int*)d_in[9];
    const int* dst_p2 = (const int*)d_in[10];
    const int* src_s2 = (const int*)d_in[11];
    const int* dst_s2 = (const int*)d_in[12];
    const float* embed_W = (const float*)d_in[13];
    const float* embed_b = (const float*)d_in[14];
    const float* mlp_W1  = (const float*)d_in[15];
    const float* mlp_b1  = (const float*)d_in[16];
    const float* ln1_g   = (const float*)d_in[17];
    const float* ln1_b   = (const float*)d_in[18];
    const float* mlp_W2  = (const float*)d_in[19];
    const float* mlp_b2  = (const float*)d_in[20];
    const float* ln2_g   = (const float*)d_in[21];
    const float* ln2_b   = (const float*)d_in[22];
    const float* Wsrc1   = (const float*)d_in[23];
    const float* bsrc1   = (const float*)d_in[24];
    const float* attn1   = (const float*)d_in[25];
    const float* Wsrc2   = (const float*)d_in[26];
    const float* bsrc2   = (const float*)d_in[27];
    const float* attn2   = (const float*)d_in[28];
    const float* out_W   = (const float*)d_in[29];
    const float* out_b   = (const float*)d_in[30];

    float *hA, *hB, *f, *yA, *sc;
    int *off, *ssrc, *cnt, *cur;
    cudaGetSymbolAddress((void**)&hA,   g_hA);
    cudaGetSymbolAddress((void**)&hB,   g_hB);
    cudaGetSymbolAddress((void**)&f,    g_f);
    cudaGetSymbolAddress((void**)&yA,   g_yA);
    cudaGetSymbolAddress((void**)&sc,   g_sc);
    cudaGetSymbolAddress((void**)&off,  g_off);
    cudaGetSymbolAddress((void**)&ssrc, g_ssrc);
    cudaGetSymbolAddress((void**)&cnt,  g_cnt);
    cudaGetSymbolAddress((void**)&cur,  g_cur);

    float* logits = (float*)d_out;
    float* yh_out = (float*)d_out + (size_t)NN * OD;

    k_detect_flag<<<1, 256>>>((const unsigned char*)flag);

    // ---- CSR sorts (dst-sorted edge lists) for the 4 relations ----
    const int* srcs_[4] = {src_p1, src_s1, src_p2, src_s2};
    const int* dsts_[4] = {dst_p1, dst_s1, dst_p2, dst_s2};
    for (int r = 0; r < 4; ++r) {
        cudaMemsetAsync(cnt, 0, sizeof(int) * NN);
        k_hist<<<(NE + 255) / 256, 256>>>(dsts_[r], cnt);
        k_scan<<<1, 1024>>>(cnt, off + r * (NN + 1), cur);
        k_scatter<<<(NE + 255) / 256, 256>>>(srcs_[r], dsts_[r], cur, ssrc + r * NE);
    }

    // ---- EmbeddingBag + MLP ----
    k_embed<<<(NN + 7) / 8, 256>>>(emb_indices, emb_offsets, emb_weights, embed_W, embed_b, hA);
    dim3 g128((NN + 63) / 64, 2);
    k_gemm_bias<<<g128, 256>>>(hA, mlp_W1, mlp_b1, f, NN, 128);
    k_ln_relu<<<NN / 8, 256>>>(f, hB, ln1_g, ln1_b);
    k_gemm_bias<<<g128, 256>>>(hB, mlp_W2, mlp_b2, f, NN, 128);
    k_ln_relu<<<NN / 8, 256>>>(f, hA, ln2_g, ln2_b);

    // ---- prop 1: x = hA -> hB, y -> yA ----
    k_gemm_bias<<<g128, 256>>>(hA, Wsrc1, bsrc1, f, NN, 128);
    k_prop<<<(NN + 7) / 8, 256>>>(f, hA, y, attn1,
                                  off + 0 * (NN + 1), ssrc + 0 * NE,
                                  off + 1 * (NN + 1), ssrc + 1 * NE,
                                  sc, sc + NE, flag, hB, yA);

    // ---- prop 2: x = hB -> hA, yA -> yh_out ----
    k_gemm_bias<<<g128, 256>>>(hB, Wsrc2, bsrc2, f, NN, 128);
    k_prop<<<(NN + 7) / 8, 256>>>(f, hB, yA, attn2,
                                  off + 2 * (NN + 1), ssrc + 2 * NE,
                                  off + 3 * (NN + 1), ssrc + 3 * NE,
                                  sc, sc + NE, flag, hA, yh_out);

    // ---- logits = h @ out_W + out_b ----
    dim3 g256((NN + 63) / 64, 4);
    k_gemm_bias<<<g256, 256>>>(hA, out_W, out_b, logits, NN, 256);
}

// round 5
// speedup vs baseline: 2.5492x; 1.2162x over previous
#include <cuda_runtime.h>
#include <math.h>

#define NN 50000
#define HD 128
#define OD 256
#define NE 800000
#define LN_EPS 1e-5f

// ---------------- scratch (static device globals; no allocation) ----------------
__device__ float g_hA[NN * HD];
__device__ float g_hB[NN * HD];
__device__ float g_f [NN * HD];
__device__ float g_yA [NN * OD];
__device__ float g_sc[2 * NE];
__device__ int   g_off [4][NN + 1];
__device__ int   g_ssrc[4][NE];
__device__ int   g_cnt[4][NN];
__device__ int   g_cur[4][NN];
__device__ int   g_flagIsInt;

// ---------------- helpers ----------------
__device__ __forceinline__ float lrelu02(float x) {
    return x >= 0.f ? x : 0.2f * x;
}

// ---------------- kernels ----------------

// Detect flag buffer layout: int32 (bytes 1..3 of each word are 0) vs uint8.
__global__ void k_detect_flag(const unsigned char* __restrict__ flag) {
    __shared__ int cnt;
    if (threadIdx.x == 0) cnt = 0;
    __syncthreads();
    int local = 0;
    for (int i = threadIdx.x; i < 4000; i += 256)
        if ((i & 3) != 0 && flag[i] != 0) local = 1;
    if (local) atomicOr(&cnt, 1);
    __syncthreads();
    if (threadIdx.x == 0) g_flagIsInt = (cnt == 0) ? 1 : 0;
}

// -------- counting sort by dst (all 4 relations in one grid via blockIdx.y) --------
__global__ void k_hist4(const int* __restrict__ d0, const int* __restrict__ d1,
                        const int* __restrict__ d2, const int* __restrict__ d3,
                        int* __restrict__ cnt) {
    int e = blockIdx.x * 256 + threadIdx.x;
    int r = blockIdx.y;
    const int* dst = r == 0 ? d0 : r == 1 ? d1 : r == 2 ? d2 : d3;
    if (e < NE) atomicAdd(&cnt[r * NN + dst[e]], 1);
}

// 4 blocks, one relation each: exclusive scan -> offs[NN+1], cur[NN]
__global__ void k_scan4(const int* __restrict__ cntAll, int* __restrict__ offsAll,
                        int* __restrict__ curAll) {
    __shared__ int part[1024];
    const int CH = (NN + 1023) / 1024;
    int r = blockIdx.x;
    const int* cnt = cntAll + r * NN;
    int* offs = offsAll + r * (NN + 1);
    int* cur  = curAll  + r * NN;
    int t = threadIdx.x;
    int lo = t * CH, hi = min(lo + CH, NN);
    int s = 0;
    for (int i = lo; i < hi; ++i) s += cnt[i];
    part[t] = s;
    __syncthreads();
    for (int o = 1; o < 1024; o <<= 1) {
        int v = (t >= o) ? part[t - o] : 0;
        __syncthreads();
        part[t] += v;
        __syncthreads();
    }
    int base = (t == 0) ? 0 : part[t - 1];
    for (int i = lo; i < hi; ++i) {
        offs[i] = base;
        cur[i]  = base;
        base += cnt[i];
    }
    if (t == 1023) offs[NN] = base;
}

__global__ void k_scatter4(const int* __restrict__ s0, const int* __restrict__ d0,
                           const int* __restrict__ s1, const int* __restrict__ d1,
                           const int* __restrict__ s2, const int* __restrict__ d2,
                           const int* __restrict__ s3, const int* __restrict__ d3,
                           int* __restrict__ cur, int* __restrict__ ssrc) {
    int e = blockIdx.x * 256 + threadIdx.x;
    int r = blockIdx.y;
    const int* src = r == 0 ? s0 : r == 1 ? s1 : r == 2 ? s2 : s3;
    const int* dst = r == 0 ? d0 : r == 1 ? d1 : r == 2 ? d2 : d3;
    if (e < NE) {
        int v = dst[e];
        int pos = atomicAdd(&cur[r * NN + v], 1);
        ssrc[r * NE + pos] = src[e];
    }
}

// EmbeddingBag(sum, per_sample_weights) + bias + relu. Warp per node.
__global__ void k_embed(const int* __restrict__ idx, const int* __restrict__ offs,
                        const float* __restrict__ wts, const float* __restrict__ table,
                        const float* __restrict__ bias, float* __restrict__ out) {
    int n = blockIdx.x * 8 + (threadIdx.x >> 5);
    if (n >= NN) return;
    int lane = threadIdx.x & 31;
    int s = offs[n], e = offs[n + 1];
    float4 acc = make_float4(0.f, 0.f, 0.f, 0.f);
    for (int base = s; base < e; base += 32) {
        int j = base + lane;
        int id = (j < e) ? idx[j] : 0;
        float w = (j < e) ? wts[j] : 0.f;
        int cnt = min(32, e - base);
        for (int t = 0; t < cnt; ++t) {
            int   uj = __shfl_sync(0xffffffffu, id, t);
            float wj = __shfl_sync(0xffffffffu, w,  t);
            float4 tv = *(const float4*)&table[(size_t)uj * HD + lane * 4];
            acc.x = fmaf(tv.x, wj, acc.x);
            acc.y = fmaf(tv.y, wj, acc.y);
            acc.z = fmaf(tv.z, wj, acc.z);
            acc.w = fmaf(tv.w, wj, acc.w);
        }
    }
    float4 b4 = *(const float4*)&bias[lane * 4];
    float4 r;
    r.x = fmaxf(acc.x + b4.x, 0.f);
    r.y = fmaxf(acc.y + b4.y, 0.f);
    r.z = fmaxf(acc.z + b4.z, 0.f);
    r.w = fmaxf(acc.w + b4.w, 0.f);
    *(float4*)&out[(size_t)n * HD + lane * 4] = r;
}

// C[n,OUT] = X[n,128] @ W[128,OUT] + Bias, optionally fused LayerNorm(128)+ReLU.
// 128x128 tile, 256 threads, 8x8 accum per thread (rows/cols in 4+4 split groups).
__global__ __launch_bounds__(256, 2)
void k_gemm(const float* __restrict__ X, const float* __restrict__ W,
            const float* __restrict__ Bias, const float* __restrict__ lng,
            const float* __restrict__ lnb, float* __restrict__ C,
            int n, int OUT, int do_ln) {
    __shared__ float xs[32][132];
    __shared__ float ws[32][132];
    int row0 = blockIdx.x * 128, col0 = blockIdx.y * 128;
    int tid = threadIdx.x;
    int tx = tid & 15, ty = tid >> 4;
    float acc[8][8] = {};
    for (int kb = 0; kb < 128; kb += 32) {
#pragma unroll
        for (int it = 0; it < 4; ++it) {
            int idx = it * 256 + tid;
            int m = idx >> 3, kq = (idx & 7) * 4;
            int row = row0 + m;
            float4 v = (row < n) ? *(const float4*)&X[(size_t)row * 128 + kb + kq]
                                 : make_float4(0.f, 0.f, 0.f, 0.f);
            xs[kq + 0][m] = v.x; xs[kq + 1][m] = v.y;
            xs[kq + 2][m] = v.z; xs[kq + 3][m] = v.w;
        }
#pragma unroll
        for (int it = 0; it < 4; ++it) {
            int idx = it * 256 + tid;
            int k = idx >> 5, cq = (idx & 31) * 4;
            *(float4*)&ws[k][cq] = *(const float4*)&W[(size_t)(kb + k) * OUT + col0 + cq];
        }
        __syncthreads();
#pragma unroll
        for (int k = 0; k < 32; ++k) {
            float4 a0 = *(const float4*)&xs[k][ty * 4];
            float4 a1 = *(const float4*)&xs[k][64 + ty * 4];
            float4 b0 = *(const float4*)&ws[k][tx * 4];
            float4 b1 = *(const float4*)&ws[k][64 + tx * 4];
            float av[8] = {a0.x, a0.y, a0.z, a0.w, a1.x, a1.y, a1.z, a1.w};
            float bv[8] = {b0.x, b0.y, b0.z, b0.w, b1.x, b1.y, b1.z, b1.w};
#pragma unroll
            for (int i = 0; i < 8; ++i)
#pragma unroll
                for (int j = 0; j < 8; ++j)
                    acc[i][j] = fmaf(av[i], bv[j], acc[i][j]);
        }
        __syncthreads();
    }
    // bias add
    float pb[8];
#pragma unroll
    for (int j = 0; j < 8; ++j) {
        int col = col0 + (j < 4 ? tx * 4 + j : 64 + tx * 4 + j - 4);
        pb[j] = Bias[col];
    }
#pragma unroll
    for (int i = 0; i < 8; ++i)
#pragma unroll
        for (int j = 0; j < 8; ++j) acc[i][j] += pb[j];

    if (do_ln) {  // OUT must be 128: block holds the entire row
        float gv[8], b2[8];
#pragma unroll
        for (int j = 0; j < 8; ++j) {
            int col = (j < 4 ? tx * 4 + j : 64 + tx * 4 + j - 4);
            gv[j] = lng[col]; b2[j] = lnb[col];
        }
#pragma unroll
        for (int i = 0; i < 8; ++i) {
            float s = 0.f;
#pragma unroll
            for (int j = 0; j < 8; ++j) s += acc[i][j];
#pragma unroll
            for (int o = 1; o < 16; o <<= 1) s += __shfl_xor_sync(0xffffffffu, s, o);
            float mu = s * (1.f / 128.f);
            float q = 0.f;
#pragma unroll
            for (int j = 0; j < 8; ++j) { float d = acc[i][j] - mu; q += d * d; }
#pragma unroll
            for (int o = 1; o < 16; o <<= 1) q += __shfl_xor_sync(0xffffffffu, q, o);
            float rs = rsqrtf(q * (1.f / 128.f) + LN_EPS);
#pragma unroll
            for (int j = 0; j < 8; ++j)
                acc[i][j] = fmaxf((acc[i][j] - mu) * rs * gv[j] + b2[j], 0.f);
        }
    }
#pragma unroll
    for (int i = 0; i < 8; ++i) {
        int row = row0 + (i < 4 ? ty * 4 + i : 64 + ty * 4 + i - 4);
        if (row < n) {
            float4 o0 = make_float4(acc[i][0], acc[i][1], acc[i][2], acc[i][3]);
            float4 o1 = make_float4(acc[i][4], acc[i][5], acc[i][6], acc[i][7]);
            *(float4*)&C[(size_t)row * OUT + col0 + tx * 4]      = o0;
            *(float4*)&C[(size_t)row * OUT + col0 + 64 + tx * 4] = o1;
        }
    }
}

// ---------------- fused per-destination prop kernel ----------------
__global__ void k_prop(const float* __restrict__ f, const float* __restrict__ x,
                       const float* __restrict__ yin, const float* __restrict__ attn,
                       const int* __restrict__ offp, const int* __restrict__ sp,
                       const int* __restrict__ offs2, const int* __restrict__ ss,
                       float* __restrict__ scp, float* __restrict__ scs,
                       const void* __restrict__ flag,
                       float* __restrict__ hout, float* __restrict__ yout) {
    int v = blockIdx.x * 8 + (threadIdx.x >> 5);
    if (v >= NN) return;
    int lane = threadIdx.x & 31;

    float4 at = *(const float4*)&attn[lane * 4];
    float4 fv = *(const float4*)&f[(size_t)v * HD + lane * 4];

    float4 accf = make_float4(0.f, 0.f, 0.f, 0.f);
    float4 ay0  = make_float4(0.f, 0.f, 0.f, 0.f);
    float4 ay1  = make_float4(0.f, 0.f, 0.f, 0.f);

#pragma unroll
    for (int rel = 0; rel < 2; ++rel) {
        const int* off  = rel ? offs2 : offp;
        const int* ssrc = rel ? ss    : sp;
        float*     sc   = rel ? scs   : scp;
        int lo = off[v], hi = off[v + 1];

        // pass A: scores + online softmax (max, den)
        float m = -__int_as_float(0x7f800000);
        float den = 0.f;
        for (int j = lo; j < hi; ++j) {
            int u = __ldg(&ssrc[j]);
            float4 fu = *(const float4*)&f[(size_t)u * HD + lane * 4];
            float p = lrelu02(fu.x + fv.x) * at.x
                    + lrelu02(fu.y + fv.y) * at.y
                    + lrelu02(fu.z + fv.z) * at.z
                    + lrelu02(fu.w + fv.w) * at.w;
#pragma unroll
            for (int o = 16; o; o >>= 1) p += __shfl_xor_sync(0xffffffffu, p, o);
            if (lane == 0) sc[j] = p;
            if (p > m) { den *= expf(m - p); m = p; }
            den += expf(p - m);
        }
        float rden = (den > 0.f) ? 1.f / den : 0.f;

        // pass B: weighted aggregation
        for (int j = lo; j < hi; ++j) {
            int u = __ldg(&ssrc[j]);
            float a = expf(sc[j] - m) * rden;
            float4 fu = *(const float4*)&f[(size_t)u * HD + lane * 4];
            accf.x = fmaf(fu.x, a, accf.x);
            accf.y = fmaf(fu.y, a, accf.y);
            accf.z = fmaf(fu.z, a, accf.z);
            accf.w = fmaf(fu.w, a, accf.w);
            float4 y0 = *(const float4*)&yin[(size_t)u * OD + lane * 4];
            float4 y1 = *(const float4*)&yin[(size_t)u * OD + 128 + lane * 4];
            ay0.x = fmaf(y0.x, a, ay0.x); ay0.y = fmaf(y0.y, a, ay0.y);
            ay0.z = fmaf(y0.z, a, ay0.z); ay0.w = fmaf(y0.w, a, ay0.w);
            ay1.x = fmaf(y1.x, a, ay1.x); ay1.y = fmaf(y1.y, a, ay1.y);
            ay1.z = fmaf(y1.z, a, ay1.z); ay1.w = fmaf(y1.w, a, ay1.w);
        }
    }

    // h epilogue: elu(agg_p + agg_s + 2*x)
    float4 xv = *(const float4*)&x[(size_t)v * HD + lane * 4];
    float4 h;
    h.x = accf.x + 2.f * xv.x; h.x = h.x > 0.f ? h.x : expm1f(h.x);
    h.y = accf.y + 2.f * xv.y; h.y = h.y > 0.f ? h.y : expm1f(h.y);
    h.z = accf.z + 2.f * xv.z; h.z = h.z > 0.f ? h.z : expm1f(h.z);
    h.w = accf.w + 2.f * xv.w; h.w = h.w > 0.f ? h.w : expm1f(h.w);
    *(float4*)&hout[(size_t)v * HD + lane * 4] = h;

    // y epilogue: normalize or copy per flag
    float q = ay0.x * ay0.x + ay0.y * ay0.y + ay0.z * ay0.z + ay0.w * ay0.w
            + ay1.x * ay1.x + ay1.y * ay1.y + ay1.z * ay1.z + ay1.w * ay1.w;
#pragma unroll
    for (int o = 16; o; o >>= 1) q += __shfl_xor_sync(0xffffffffu, q, o);
    float inv = 1.f / fmaxf(sqrtf(q), 1e-12f);
    bool fl;
    if (g_flagIsInt) fl = ((const int*)flag)[v] != 0;
    else             fl = ((const unsigned char*)flag)[v] != 0;
    size_t base = (size_t)v * OD + lane * 4;
    float4 r0, r1;
    if (fl) {
        r0 = *(const float4*)&yin[base];
        r1 = *(const float4*)&yin[base + 128];
    } else {
        r0 = make_float4(ay0.x * inv, ay0.y * inv, ay0.z * inv, ay0.w * inv);
        r1 = make_float4(ay1.x * inv, ay1.y * inv, ay1.z * inv, ay1.w * inv);
    }
    *(float4*)&yout[base]       = r0;
    *(float4*)&yout[base + 128] = r1;
}

// ---------------- host orchestration ----------------
extern "C" void kernel_launch(void* const* d_in, const int* in_sizes, int n_in,
                              void* d_out, int out_size) {
    const int*   emb_indices = (const int*)  d_in[0];
    const int*   emb_offsets = (const int*)  d_in[1];
    const float* emb_weights = (const float*)d_in[2];
    const float* y           = (const float*)d_in[3];
    const void*  flag        = d_in[4];
    const int* src_p1 = (const int*)d_in[5];
    const int* dst_p1 = (const int*)d_in[6];
    const int* src_s1 = (const int*)d_in[7];
    const int* dst_s1 = (const int*)d_in[8];
    const int* src_p2 = (const int*)d_in[9];
    const int* dst_p2 = (const int*)d_in[10];
    const int* src_s2 = (const int*)d_in[11];
    const int* dst_s2 = (const int*)d_in[12];
    const float* embed_W = (const float*)d_in[13];
    const float* embed_b = (const float*)d_in[14];
    const float* mlp_W1  = (const float*)d_in[15];
    const float* mlp_b1  = (const float*)d_in[16];
    const float* ln1_g   = (const float*)d_in[17];
    const float* ln1_b   = (const float*)d_in[18];
    const float* mlp_W2  = (const float*)d_in[19];
    const float* mlp_b2  = (const float*)d_in[20];
    const float* ln2_g   = (const float*)d_in[21];
    const float* ln2_b   = (const float*)d_in[22];
    const float* Wsrc1   = (const float*)d_in[23];
    const float* bsrc1   = (const float*)d_in[24];
    const float* attn1   = (const float*)d_in[25];
    const float* Wsrc2   = (const float*)d_in[26];
    const float* bsrc2   = (const float*)d_in[27];
    const float* attn2   = (const float*)d_in[28];
    const float* out_W   = (const float*)d_in[29];
    const float* out_b   = (const float*)d_in[30];

    float *hA, *hB, *f, *yA, *sc;
    int *off, *ssrc, *cnt, *cur;
    cudaGetSymbolAddress((void**)&hA,   g_hA);
    cudaGetSymbolAddress((void**)&hB,   g_hB);
    cudaGetSymbolAddress((void**)&f,    g_f);
    cudaGetSymbolAddress((void**)&yA,   g_yA);
    cudaGetSymbolAddress((void**)&sc,   g_sc);
    cudaGetSymbolAddress((void**)&off,  g_off);
    cudaGetSymbolAddress((void**)&ssrc, g_ssrc);
    cudaGetSymbolAddress((void**)&cnt,  g_cnt);
    cudaGetSymbolAddress((void**)&cur,  g_cur);

    float* logits = (float*)d_out;
    float* yh_out = (float*)d_out + (size_t)NN * OD;

    k_detect_flag<<<1, 256>>>((const unsigned char*)flag);

    // ---- CSR sorts (dst-sorted edge lists) for the 4 relations ----
    cudaMemsetAsync(cnt, 0, sizeof(int) * 4 * NN);
    dim3 ge((NE + 255) / 256, 4);
    k_hist4<<<ge, 256>>>(dst_p1, dst_s1, dst_p2, dst_s2, cnt);
    k_scan4<<<4, 1024>>>(cnt, off, cur);
    k_scatter4<<<ge, 256>>>(src_p1, dst_p1, src_s1, dst_s1,
                            src_p2, dst_p2, src_s2, dst_s2, cur, ssrc);

    // ---- EmbeddingBag + MLP (LN fused into GEMM epilogue) ----
    k_embed<<<(NN + 7) / 8, 256>>>(emb_indices, emb_offsets, emb_weights, embed_W, embed_b, hA);
    dim3 g1((NN + 127) / 128, 1);
    k_gemm<<<g1, 256>>>(hA, mlp_W1, mlp_b1, ln1_g, ln1_b, hB, NN, 128, 1);
    k_gemm<<<g1, 256>>>(hB, mlp_W2, mlp_b2, ln2_g, ln2_b, hA, NN, 128, 1);

    // ---- prop 1: x = hA -> hB, y -> yA ----
    k_gemm<<<g1, 256>>>(hA, Wsrc1, bsrc1, nullptr, nullptr, f, NN, 128, 0);
    k_prop<<<(NN + 7) / 8, 256>>>(f, hA, y, attn1,
                                  off + 0 * (NN + 1), ssrc + 0 * NE,
                                  off + 1 * (NN + 1), ssrc + 1 * NE,
                                  sc, sc + NE, flag, hB, yA);

    // ---- prop 2: x = hB -> hA, yA -> yh_out ----
    k_gemm<<<g1, 256>>>(hB, Wsrc2, bsrc2, nullptr, nullptr, f, NN, 128, 0);
    k_prop<<<(NN + 7) / 8, 256>>>(f, hB, yA, attn2,
                                  off + 2 * (NN + 1), ssrc + 2 * NE,
                                  off + 3 * (NN + 1), ssrc + 3 * NE,
                                  sc, sc + NE, flag, hA, yh_out);

    // ---- logits = h @ out_W + out_b ----
    dim3 g2((NN + 127) / 128, 2);
    k_gemm<<<g2, 256>>>(hA, out_W, out_b, nullptr, nullptr, logits, NN, 256, 0);
}

// round 6
// speedup vs baseline: 2.5842x; 1.0137x over previous
#include <cuda_runtime.h>
#include <math.h>

#define NN 50000
#define HD 128
#define OD 256
#define NE 800000
#define LN_EPS 1e-5f

// ---------------- scratch (static device globals; no allocation) ----------------
__device__ float g_hA[NN * HD];
__device__ float g_hB[NN * HD];
__device__ float g_f [NN * HD];
__device__ float g_yA [NN * OD];
__device__ int   g_off [4][NN + 1];
__device__ int   g_ssrc[4][NE];
__device__ int   g_cnt[4][NN];
__device__ int   g_cur[4][NN];
__device__ int   g_flagIsInt;

// ---------------- helpers ----------------
__device__ __forceinline__ float lrelu02(float x) {
    return x >= 0.f ? x : 0.2f * x;
}

// ---------------- kernels ----------------

// Detect flag buffer layout: int32 (bytes 1..3 of each word are 0) vs uint8.
__global__ void k_detect_flag(const unsigned char* __restrict__ flag) {
    __shared__ int cnt;
    if (threadIdx.x == 0) cnt = 0;
    __syncthreads();
    int local = 0;
    for (int i = threadIdx.x; i < 4000; i += 256)
        if ((i & 3) != 0 && flag[i] != 0) local = 1;
    if (local) atomicOr(&cnt, 1);
    __syncthreads();
    if (threadIdx.x == 0) g_flagIsInt = (cnt == 0) ? 1 : 0;
}

// -------- counting sort by dst (all 4 relations in one grid via blockIdx.y) --------
__global__ void k_hist4(const int* __restrict__ d0, const int* __restrict__ d1,
                        const int* __restrict__ d2, const int* __restrict__ d3,
                        int* __restrict__ cnt) {
    int e = blockIdx.x * 256 + threadIdx.x;
    int r = blockIdx.y;
    const int* dst = r == 0 ? d0 : r == 1 ? d1 : r == 2 ? d2 : d3;
    if (e < NE) atomicAdd(&cnt[r * NN + dst[e]], 1);
}

// 4 blocks, one relation each: exclusive scan -> offs[NN+1], cur[NN]
__global__ void k_scan4(const int* __restrict__ cntAll, int* __restrict__ offsAll,
                        int* __restrict__ curAll) {
    __shared__ int part[1024];
    const int CH = (NN + 1023) / 1024;
    int r = blockIdx.x;
    const int* cnt = cntAll + r * NN;
    int* offs = offsAll + r * (NN + 1);
    int* cur  = curAll  + r * NN;
    int t = threadIdx.x;
    int lo = t * CH, hi = min(lo + CH, NN);
    int s = 0;
    for (int i = lo; i < hi; ++i) s += cnt[i];
    part[t] = s;
    __syncthreads();
    for (int o = 1; o < 1024; o <<= 1) {
        int v = (t >= o) ? part[t - o] : 0;
        __syncthreads();
        part[t] += v;
        __syncthreads();
    }
    int base = (t == 0) ? 0 : part[t - 1];
    for (int i = lo; i < hi; ++i) {
        offs[i] = base;
        cur[i]  = base;
        base += cnt[i];
    }
    if (t == 1023) offs[NN] = base;
}

__global__ void k_scatter4(const int* __restrict__ s0, const int* __restrict__ d0,
                           const int* __restrict__ s1, const int* __restrict__ d1,
                           const int* __restrict__ s2, const int* __restrict__ d2,
                           const int* __restrict__ s3, const int* __restrict__ d3,
                           int* __restrict__ cur, int* __restrict__ ssrc) {
    int e = blockIdx.x * 256 + threadIdx.x;
    int r = blockIdx.y;
    const int* src = r == 0 ? s0 : r == 1 ? s1 : r == 2 ? s2 : s3;
    const int* dst = r == 0 ? d0 : r == 1 ? d1 : r == 2 ? d2 : d3;
    if (e < NE) {
        int v = dst[e];
        int pos = atomicAdd(&cur[r * NN + v], 1);
        ssrc[r * NE + pos] = src[e];
    }
}

// EmbeddingBag(sum, per_sample_weights) + bias + relu. Warp per node.
__global__ void k_embed(const int* __restrict__ idx, const int* __restrict__ offs,
                        const float* __restrict__ wts, const float* __restrict__ table,
                        const float* __restrict__ bias, float* __restrict__ out) {
    int n = blockIdx.x * 8 + (threadIdx.x >> 5);
    if (n >= NN) return;
    int lane = threadIdx.x & 31;
    int s = offs[n], e = offs[n + 1];
    float4 acc = make_float4(0.f, 0.f, 0.f, 0.f);
    for (int base = s; base < e; base += 32) {
        int j = base + lane;
        int id = (j < e) ? idx[j] : 0;
        float w = (j < e) ? wts[j] : 0.f;
        int cnt = min(32, e - base);
        for (int t = 0; t < cnt; ++t) {
            int   uj = __shfl_sync(0xffffffffu, id, t);
            float wj = __shfl_sync(0xffffffffu, w,  t);
            float4 tv = *(const float4*)&table[(size_t)uj * HD + lane * 4];
            acc.x = fmaf(tv.x, wj, acc.x);
            acc.y = fmaf(tv.y, wj, acc.y);
            acc.z = fmaf(tv.z, wj, acc.z);
            acc.w = fmaf(tv.w, wj, acc.w);
        }
    }
    float4 b4 = *(const float4*)&bias[lane * 4];
    float4 r;
    r.x = fmaxf(acc.x + b4.x, 0.f);
    r.y = fmaxf(acc.y + b4.y, 0.f);
    r.z = fmaxf(acc.z + b4.z, 0.f);
    r.w = fmaxf(acc.w + b4.w, 0.f);
    *(float4*)&out[(size_t)n * HD + lane * 4] = r;
}

// C[n,OUT] = X[n,128] @ W[128,OUT] + Bias, optionally fused LayerNorm(128)+ReLU.
// 128x128 tile, 256 threads, 8x8 accum per thread (rows/cols in 4+4 split groups).
__global__ __launch_bounds__(256, 2)
void k_gemm(const float* __restrict__ X, const float* __restrict__ W,
            const float* __restrict__ Bias, const float* __restrict__ lng,
            const float* __restrict__ lnb, float* __restrict__ C,
            int n, int OUT, int do_ln) {
    __shared__ float xs[32][132];
    __shared__ float ws[32][132];
    int row0 = blockIdx.x * 128, col0 = blockIdx.y * 128;
    int tid = threadIdx.x;
    int tx = tid & 15, ty = tid >> 4;
    float acc[8][8] = {};
    for (int kb = 0; kb < 128; kb += 32) {
#pragma unroll
        for (int it = 0; it < 4; ++it) {
            int idx = it * 256 + tid;
            int m = idx >> 3, kq = (idx & 7) * 4;
            int row = row0 + m;
            float4 v = (row < n) ? *(const float4*)&X[(size_t)row * 128 + kb + kq]
                                 : make_float4(0.f, 0.f, 0.f, 0.f);
            xs[kq + 0][m] = v.x; xs[kq + 1][m] = v.y;
            xs[kq + 2][m] = v.z; xs[kq + 3][m] = v.w;
        }
#pragma unroll
        for (int it = 0; it < 4; ++it) {
            int idx = it * 256 + tid;
            int k = idx >> 5, cq = (idx & 31) * 4;
            *(float4*)&ws[k][cq] = *(const float4*)&W[(size_t)(kb + k) * OUT + col0 + cq];
        }
        __syncthreads();
#pragma unroll
        for (int k = 0; k < 32; ++k) {
            float4 a0 = *(const float4*)&xs[k][ty * 4];
            float4 a1 = *(const float4*)&xs[k][64 + ty * 4];
            float4 b0 = *(const float4*)&ws[k][tx * 4];
            float4 b1 = *(const float4*)&ws[k][64 + tx * 4];
            float av[8] = {a0.x, a0.y, a0.z, a0.w, a1.x, a1.y, a1.z, a1.w};
            float bv[8] = {b0.x, b0.y, b0.z, b0.w, b1.x, b1.y, b1.z, b1.w};
#pragma unroll
            for (int i = 0; i < 8; ++i)
#pragma unroll
                for (int j = 0; j < 8; ++j)
                    acc[i][j] = fmaf(av[i], bv[j], acc[i][j]);
        }
        __syncthreads();
    }
    // bias add
    float pb[8];
#pragma unroll
    for (int j = 0; j < 8; ++j) {
        int col = col0 + (j < 4 ? tx * 4 + j : 64 + tx * 4 + j - 4);
        pb[j] = Bias[col];
    }
#pragma unroll
    for (int i = 0; i < 8; ++i)
#pragma unroll
        for (int j = 0; j < 8; ++j) acc[i][j] += pb[j];

    if (do_ln) {  // OUT must be 128: block holds the entire row
        float gv[8], b2[8];
#pragma unroll
        for (int j = 0; j < 8; ++j) {
            int col = (j < 4 ? tx * 4 + j : 64 + tx * 4 + j - 4);
            gv[j] = lng[col]; b2[j] = lnb[col];
        }
#pragma unroll
        for (int i = 0; i < 8; ++i) {
            float s = 0.f;
#pragma unroll
            for (int j = 0; j < 8; ++j) s += acc[i][j];
#pragma unroll
            for (int o = 1; o < 16; o <<= 1) s += __shfl_xor_sync(0xffffffffu, s, o);
            float mu = s * (1.f / 128.f);
            float q = 0.f;
#pragma unroll
            for (int j = 0; j < 8; ++j) { float d = acc[i][j] - mu; q += d * d; }
#pragma unroll
            for (int o = 1; o < 16; o <<= 1) q += __shfl_xor_sync(0xffffffffu, q, o);
            float rs = rsqrtf(q * (1.f / 128.f) + LN_EPS);
#pragma unroll
            for (int j = 0; j < 8; ++j)
                acc[i][j] = fmaxf((acc[i][j] - mu) * rs * gv[j] + b2[j], 0.f);
        }
    }
#pragma unroll
    for (int i = 0; i < 8; ++i) {
        int row = row0 + (i < 4 ? ty * 4 + i : 64 + ty * 4 + i - 4);
        if (row < n) {
            float4 o0 = make_float4(acc[i][0], acc[i][1], acc[i][2], acc[i][3]);
            float4 o1 = make_float4(acc[i][4], acc[i][5], acc[i][6], acc[i][7]);
            *(float4*)&C[(size_t)row * OUT + col0 + tx * 4]      = o0;
            *(float4*)&C[(size_t)row * OUT + col0 + 64 + tx * 4] = o1;
        }
    }
}

// ---------------- fused per-destination prop kernel (single-pass online softmax) ----
// Warp per dst node. For each relation: gather f[u] ONCE per edge, compute the
// leaky-relu attention score, and immediately accumulate exp-weighted f and y
// with flash-style rescaling when the running max improves. Normalize per
// relation, then apply elu-residual (h) and normalize/flag (yh) epilogues.
__global__ void k_prop(const float* __restrict__ f, const float* __restrict__ x,
                       const float* __restrict__ yin, const float* __restrict__ attn,
                       const int* __restrict__ offp, const int* __restrict__ sp,
                       const int* __restrict__ offs2, const int* __restrict__ ss,
                       const void* __restrict__ flag,
                       float* __restrict__ hout, float* __restrict__ yout) {
    int v = blockIdx.x * 8 + (threadIdx.x >> 5);
    if (v >= NN) return;
    int lane = threadIdx.x & 31;

    float4 at = *(const float4*)&attn[lane * 4];
    float4 fv = *(const float4*)&f[(size_t)v * HD + lane * 4];

    float4 tf  = make_float4(0.f, 0.f, 0.f, 0.f);   // final feature agg (both rels)
    float4 ty0 = make_float4(0.f, 0.f, 0.f, 0.f);   // final label agg
    float4 ty1 = make_float4(0.f, 0.f, 0.f, 0.f);

#pragma unroll
    for (int rel = 0; rel < 2; ++rel) {
        const int* off  = rel ? offs2 : offp;
        const int* ssrc = rel ? ss    : sp;
        int lo = off[v], hi = off[v + 1];

        float m   = -__int_as_float(0x7f800000);  // -inf
        float den = 0.f;
        float4 af  = make_float4(0.f, 0.f, 0.f, 0.f);
        float4 ay0 = make_float4(0.f, 0.f, 0.f, 0.f);
        float4 ay1 = make_float4(0.f, 0.f, 0.f, 0.f);

        for (int j = lo; j < hi; ++j) {
            int u = __ldg(&ssrc[j]);
            float4 fu = *(const float4*)&f[(size_t)u * HD + lane * 4];
            float p = lrelu02(fu.x + fv.x) * at.x
                    + lrelu02(fu.y + fv.y) * at.y
                    + lrelu02(fu.z + fv.z) * at.z
                    + lrelu02(fu.w + fv.w) * at.w;
#pragma unroll
            for (int o = 16; o; o >>= 1) p += __shfl_xor_sync(0xffffffffu, p, o);
            if (p > m) {
                float r = expf(m - p);   // 0 on first edge (m = -inf)
                den *= r;
                af.x *= r;  af.y *= r;  af.z *= r;  af.w *= r;
                ay0.x *= r; ay0.y *= r; ay0.z *= r; ay0.w *= r;
                ay1.x *= r; ay1.y *= r; ay1.z *= r; ay1.w *= r;
                m = p;
            }
            float w = expf(p - m);
            den += w;
            af.x = fmaf(fu.x, w, af.x);
            af.y = fmaf(fu.y, w, af.y);
            af.z = fmaf(fu.z, w, af.z);
            af.w = fmaf(fu.w, w, af.w);
            float4 y0 = *(const float4*)&yin[(size_t)u * OD + lane * 4];
            float4 y1 = *(const float4*)&yin[(size_t)u * OD + 128 + lane * 4];
            ay0.x = fmaf(y0.x, w, ay0.x); ay0.y = fmaf(y0.y, w, ay0.y);
            ay0.z = fmaf(y0.z, w, ay0.z); ay0.w = fmaf(y0.w, w, ay0.w);
            ay1.x = fmaf(y1.x, w, ay1.x); ay1.y = fmaf(y1.y, w, ay1.y);
            ay1.z = fmaf(y1.z, w, ay1.z); ay1.w = fmaf(y1.w, w, ay1.w);
        }
        float rden = (den > 0.f) ? 1.f / den : 0.f;
        tf.x  = fmaf(af.x,  rden, tf.x);  tf.y  = fmaf(af.y,  rden, tf.y);
        tf.z  = fmaf(af.z,  rden, tf.z);  tf.w  = fmaf(af.w,  rden, tf.w);
        ty0.x = fmaf(ay0.x, rden, ty0.x); ty0.y = fmaf(ay0.y, rden, ty0.y);
        ty0.z = fmaf(ay0.z, rden, ty0.z); ty0.w = fmaf(ay0.w, rden, ty0.w);
        ty1.x = fmaf(ay1.x, rden, ty1.x); ty1.y = fmaf(ay1.y, rden, ty1.y);
        ty1.z = fmaf(ay1.z, rden, ty1.z); ty1.w = fmaf(ay1.w, rden, ty1.w);
    }

    // h epilogue: elu(agg_p + agg_s + 2*x)
    float4 xv = *(const float4*)&x[(size_t)v * HD + lane * 4];
    float4 h;
    h.x = tf.x + 2.f * xv.x; h.x = h.x > 0.f ? h.x : expm1f(h.x);
    h.y = tf.y + 2.f * xv.y; h.y = h.y > 0.f ? h.y : expm1f(h.y);
    h.z = tf.z + 2.f * xv.z; h.z = h.z > 0.f ? h.z : expm1f(h.z);
    h.w = tf.w + 2.f * xv.w; h.w = h.w > 0.f ? h.w : expm1f(h.w);
    *(float4*)&hout[(size_t)v * HD + lane * 4] = h;

    // y epilogue: normalize or copy per flag
    float q = ty0.x * ty0.x + ty0.y * ty0.y + ty0.z * ty0.z + ty0.w * ty0.w
            + ty1.x * ty1.x + ty1.y * ty1.y + ty1.z * ty1.z + ty1.w * ty1.w;
#pragma unroll
    for (int o = 16; o; o >>= 1) q += __shfl_xor_sync(0xffffffffu, q, o);
    float inv = 1.f / fmaxf(sqrtf(q), 1e-12f);
    bool fl;
    if (g_flagIsInt) fl = ((const int*)flag)[v] != 0;
    else             fl = ((const unsigned char*)flag)[v] != 0;
    size_t base = (size_t)v * OD + lane * 4;
    float4 r0, r1;
    if (fl) {
        r0 = *(const float4*)&yin[base];
        r1 = *(const float4*)&yin[base + 128];
    } else {
        r0 = make_float4(ty0.x * inv, ty0.y * inv, ty0.z * inv, ty0.w * inv);
        r1 = make_float4(ty1.x * inv, ty1.y * inv, ty1.z * inv, ty1.w * inv);
    }
    *(float4*)&yout[base]       = r0;
    *(float4*)&yout[base + 128] = r1;
}

// ---------------- host orchestration ----------------
extern "C" void kernel_launch(void* const* d_in, const int* in_sizes, int n_in,
                              void* d_out, int out_size) {
    const int*   emb_indices = (const int*)  d_in[0];
    const int*   emb_offsets = (const int*)  d_in[1];
    const float* emb_weights = (const float*)d_in[2];
    const float* y           = (const float*)d_in[3];
    const void*  flag        = d_in[4];
    const int* src_p1 = (const int*)d_in[5];
    const int* dst_p1 = (const int*)d_in[6];
    const int* src_s1 = (const int*)d_in[7];
    const int* dst_s1 = (const int*)d_in[8];
    const int* src_p2 = (const int*)d_in[9];
    const int* dst_p2 = (const int*)d_in[10];
    const int* src_s2 = (const int*)d_in[11];
    const int* dst_s2 = (const int*)d_in[12];
    const float* embed_W = (const float*)d_in[13];
    const float* embed_b = (const float*)d_in[14];
    const float* mlp_W1  = (const float*)d_in[15];
    const float* mlp_b1  = (const float*)d_in[16];
    const float* ln1_g   = (const float*)d_in[17];
    const float* ln1_b   = (const float*)d_in[18];
    const float* mlp_W2  = (const float*)d_in[19];
    const float* mlp_b2  = (const float*)d_in[20];
    const float* ln2_g   = (const float*)d_in[21];
    const float* ln2_b   = (const float*)d_in[22];
    const float* Wsrc1   = (const float*)d_in[23];
    const float* bsrc1   = (const float*)d_in[24];
    const float* attn1   = (const float*)d_in[25];
    const float* Wsrc2   = (const float*)d_in[26];
    const float* bsrc2   = (const float*)d_in[27];
    const float* attn2   = (const float*)d_in[28];
    const float* out_W   = (const float*)d_in[29];
    const float* out_b   = (const float*)d_in[30];

    float *hA, *hB, *f, *yA;
    int *off, *ssrc, *cnt, *cur;
    cudaGetSymbolAddress((void**)&hA,   g_hA);
    cudaGetSymbolAddress((void**)&hB,   g_hB);
    cudaGetSymbolAddress((void**)&f,    g_f);
    cudaGetSymbolAddress((void**)&yA,   g_yA);
    cudaGetSymbolAddress((void**)&off,  g_off);
    cudaGetSymbolAddress((void**)&ssrc, g_ssrc);
    cudaGetSymbolAddress((void**)&cnt,  g_cnt);
    cudaGetSymbolAddress((void**)&cur,  g_cur);

    float* logits = (float*)d_out;
    float* yh_out = (float*)d_out + (size_t)NN * OD;

    k_detect_flag<<<1, 256>>>((const unsigned char*)flag);

    // ---- CSR sorts (dst-sorted edge lists) for the 4 relations ----
    cudaMemsetAsync(cnt, 0, sizeof(int) * 4 * NN);
    dim3 ge((NE + 255) / 256, 4);
    k_hist4<<<ge, 256>>>(dst_p1, dst_s1, dst_p2, dst_s2, cnt);
    k_scan4<<<4, 1024>>>(cnt, off, cur);
    k_scatter4<<<ge, 256>>>(src_p1, dst_p1, src_s1, dst_s1,
                            src_p2, dst_p2, src_s2, dst_s2, cur, ssrc);

    // ---- EmbeddingBag + MLP (LN fused into GEMM epilogue) ----
    k_embed<<<(NN + 7) / 8, 256>>>(emb_indices, emb_offsets, emb_weights, embed_W, embed_b, hA);
    dim3 g1((NN + 127) / 128, 1);
    k_gemm<<<g1, 256>>>(hA, mlp_W1, mlp_b1, ln1_g, ln1_b, hB, NN, 128, 1);
    k_gemm<<<g1, 256>>>(hB, mlp_W2, mlp_b2, ln2_g, ln2_b, hA, NN, 128, 1);

    // ---- prop 1: x = hA -> hB, y -> yA ----
    k_gemm<<<g1, 256>>>(hA, Wsrc1, bsrc1, nullptr, nullptr, f, NN, 128, 0);
    k_prop<<<(NN + 7) / 8, 256>>>(f, hA, y, attn1,
                                  off + 0 * (NN + 1), ssrc + 0 * NE,
                                  off + 1 * (NN + 1), ssrc + 1 * NE,
                                  flag, hB, yA);

    // ---- prop 2: x = hB -> hA, yA -> yh_out ----
    k_gemm<<<g1, 256>>>(hB, Wsrc2, bsrc2, nullptr, nullptr, f, NN, 128, 0);
    k_prop<<<(NN + 7) / 8, 256>>>(f, hB, yA, attn2,
                                  off + 2 * (NN + 1), ssrc + 2 * NE,
                                  off + 3 * (NN + 1), ssrc + 3 * NE,
                                  flag, hA, yh_out);

    // ---- logits = h @ out_W + out_b ----
    dim3 g2((NN + 127) / 128, 2);
    k_gemm<<<g2, 256>>>(hA, out_W, out_b, nullptr, nullptr, logits, NN, 256, 0);
}

// round 7
// speedup vs baseline: 2.6631x; 1.0305x over previous
#include <cuda_runtime.h>
#include <math.h>

#define NN 50000
#define HD 128
#define OD 256
#define NE 800000
#define LN_EPS 1e-5f

// ---------------- scratch (static device globals; no allocation) ----------------
__device__ float g_hA[NN * HD];
__device__ float g_hB[NN * HD];
__device__ float g_f [NN * HD];
__device__ float g_yA [NN * OD];
__device__ int   g_off [4][NN + 1];
__device__ int   g_ssrc[4][NE];
__device__ int   g_cnt[4][NN];
__device__ int   g_cur[4][NN];
__device__ int   g_flagIsInt;

// ---------------- helpers ----------------
__device__ __forceinline__ float lrelu02(float x) {
    return x >= 0.f ? x : 0.2f * x;
}

// ---------------- kernels ----------------

// Detect flag buffer layout: int32 (bytes 1..3 of each word are 0) vs uint8.
__global__ void k_detect_flag(const unsigned char* __restrict__ flag) {
    __shared__ int cnt;
    if (threadIdx.x == 0) cnt = 0;
    __syncthreads();
    int local = 0;
    for (int i = threadIdx.x; i < 4000; i += 256)
        if ((i & 3) != 0 && flag[i] != 0) local = 1;
    if (local) atomicOr(&cnt, 1);
    __syncthreads();
    if (threadIdx.x == 0) g_flagIsInt = (cnt == 0) ? 1 : 0;
}

// -------- counting sort by dst (all 4 relations in one grid via blockIdx.y) --------
__global__ void k_hist4(const int* __restrict__ d0, const int* __restrict__ d1,
                        const int* __restrict__ d2, const int* __restrict__ d3,
                        int* __restrict__ cnt) {
    int e = blockIdx.x * 256 + threadIdx.x;
    int r = blockIdx.y;
    const int* dst = r == 0 ? d0 : r == 1 ? d1 : r == 2 ? d2 : d3;
    if (e < NE) atomicAdd(&cnt[r * NN + dst[e]], 1);
}

// 4 blocks, one relation each: exclusive scan -> offs[NN+1], cur[NN]
__global__ void k_scan4(const int* __restrict__ cntAll, int* __restrict__ offsAll,
                        int* __restrict__ curAll) {
    __shared__ int part[1024];
    const int CH = (NN + 1023) / 1024;
    int r = blockIdx.x;
    const int* cnt = cntAll + r * NN;
    int* offs = offsAll + r * (NN + 1);
    int* cur  = curAll  + r * NN;
    int t = threadIdx.x;
    int lo = t * CH, hi = min(lo + CH, NN);
    int s = 0;
    for (int i = lo; i < hi; ++i) s += cnt[i];
    part[t] = s;
    __syncthreads();
    for (int o = 1; o < 1024; o <<= 1) {
        int v = (t >= o) ? part[t - o] : 0;
        __syncthreads();
        part[t] += v;
        __syncthreads();
    }
    int base = (t == 0) ? 0 : part[t - 1];
    for (int i = lo; i < hi; ++i) {
        offs[i] = base;
        cur[i]  = base;
        base += cnt[i];
    }
    if (t == 1023) offs[NN] = base;
}

__global__ void k_scatter4(const int* __restrict__ s0, const int* __restrict__ d0,
                           const int* __restrict__ s1, const int* __restrict__ d1,
                           const int* __restrict__ s2, const int* __restrict__ d2,
                           const int* __restrict__ s3, const int* __restrict__ d3,
                           int* __restrict__ cur, int* __restrict__ ssrc) {
    int e = blockIdx.x * 256 + threadIdx.x;
    int r = blockIdx.y;
    const int* src = r == 0 ? s0 : r == 1 ? s1 : r == 2 ? s2 : s3;
    const int* dst = r == 0 ? d0 : r == 1 ? d1 : r == 2 ? d2 : d3;
    if (e < NE) {
        int v = dst[e];
        int pos = atomicAdd(&cur[r * NN + v], 1);
        ssrc[r * NE + pos] = src[e];
    }
}

// EmbeddingBag(sum, per_sample_weights) + bias + relu. Warp per node.
__global__ void k_embed(const int* __restrict__ idx, const int* __restrict__ offs,
                        const float* __restrict__ wts, const float* __restrict__ table,
                        const float* __restrict__ bias, float* __restrict__ out) {
    int n = blockIdx.x * 8 + (threadIdx.x >> 5);
    if (n >= NN) return;
    int lane = threadIdx.x & 31;
    int s = offs[n], e = offs[n + 1];
    float4 acc = make_float4(0.f, 0.f, 0.f, 0.f);
    for (int base = s; base < e; base += 32) {
        int j = base + lane;
        int id = (j < e) ? idx[j] : 0;
        float w = (j < e) ? wts[j] : 0.f;
        int cnt = min(32, e - base);
#pragma unroll 2
        for (int t = 0; t < cnt; ++t) {
            int   uj = __shfl_sync(0xffffffffu, id, t);
            float wj = __shfl_sync(0xffffffffu, w,  t);
            float4 tv = *(const float4*)&table[(size_t)uj * HD + lane * 4];
            acc.x = fmaf(tv.x, wj, acc.x);
            acc.y = fmaf(tv.y, wj, acc.y);
            acc.z = fmaf(tv.z, wj, acc.z);
            acc.w = fmaf(tv.w, wj, acc.w);
        }
    }
    float4 b4 = *(const float4*)&bias[lane * 4];
    float4 r;
    r.x = fmaxf(acc.x + b4.x, 0.f);
    r.y = fmaxf(acc.y + b4.y, 0.f);
    r.z = fmaxf(acc.z + b4.z, 0.f);
    r.w = fmaxf(acc.w + b4.w, 0.f);
    *(float4*)&out[(size_t)n * HD + lane * 4] = r;
}

// C[n,OUT] = X[n,128] @ W[128,OUT] + Bias, optionally fused LayerNorm(128)+ReLU.
// 128x128 tile, 256 threads, 8x8 accum per thread (rows/cols in 4+4 split groups).
__global__ __launch_bounds__(256, 2)
void k_gemm(const float* __restrict__ X, const float* __restrict__ W,
            const float* __restrict__ Bias, const float* __restrict__ lng,
            const float* __restrict__ lnb, float* __restrict__ C,
            int n, int OUT, int do_ln) {
    __shared__ float xs[32][132];
    __shared__ float ws[32][132];
    int row0 = blockIdx.x * 128, col0 = blockIdx.y * 128;
    int tid = threadIdx.x;
    int tx = tid & 15, ty = tid >> 4;
    float acc[8][8] = {};
    for (int kb = 0; kb < 128; kb += 32) {
#pragma unroll
        for (int it = 0; it < 4; ++it) {
            int idx = it * 256 + tid;
            int m = idx >> 3, kq = (idx & 7) * 4;
            int row = row0 + m;
            float4 v = (row < n) ? *(const float4*)&X[(size_t)row * 128 + kb + kq]
                                 : make_float4(0.f, 0.f, 0.f, 0.f);
            xs[kq + 0][m] = v.x; xs[kq + 1][m] = v.y;
            xs[kq + 2][m] = v.z; xs[kq + 3][m] = v.w;
        }
#pragma unroll
        for (int it = 0; it < 4; ++it) {
            int idx = it * 256 + tid;
            int k = idx >> 5, cq = (idx & 31) * 4;
            *(float4*)&ws[k][cq] = *(const float4*)&W[(size_t)(kb + k) * OUT + col0 + cq];
        }
        __syncthreads();
#pragma unroll
        for (int k = 0; k < 32; ++k) {
            float4 a0 = *(const float4*)&xs[k][ty * 4];
            float4 a1 = *(const float4*)&xs[k][64 + ty * 4];
            float4 b0 = *(const float4*)&ws[k][tx * 4];
            float4 b1 = *(const float4*)&ws[k][64 + tx * 4];
            float av[8] = {a0.x, a0.y, a0.z, a0.w, a1.x, a1.y, a1.z, a1.w};
            float bv[8] = {b0.x, b0.y, b0.z, b0.w, b1.x, b1.y, b1.z, b1.w};
#pragma unroll
            for (int i = 0; i < 8; ++i)
#pragma unroll
                for (int j = 0; j < 8; ++j)
                    acc[i][j] = fmaf(av[i], bv[j], acc[i][j]);
        }
        __syncthreads();
    }
    // bias add
    float pb[8];
#pragma unroll
    for (int j = 0; j < 8; ++j) {
        int col = col0 + (j < 4 ? tx * 4 + j : 64 + tx * 4 + j - 4);
        pb[j] = Bias[col];
    }
#pragma unroll
    for (int i = 0; i < 8; ++i)
#pragma unroll
        for (int j = 0; j < 8; ++j) acc[i][j] += pb[j];

    if (do_ln) {  // OUT must be 128: block holds the entire row
        float gv[8], b2[8];
#pragma unroll
        for (int j = 0; j < 8; ++j) {
            int col = (j < 4 ? tx * 4 + j : 64 + tx * 4 + j - 4);
            gv[j] = lng[col]; b2[j] = lnb[col];
        }
#pragma unroll
        for (int i = 0; i < 8; ++i) {
            float s = 0.f;
#pragma unroll
            for (int j = 0; j < 8; ++j) s += acc[i][j];
#pragma unroll
            for (int o = 1; o < 16; o <<= 1) s += __shfl_xor_sync(0xffffffffu, s, o);
            float mu = s * (1.f / 128.f);
            float q = 0.f;
#pragma unroll
            for (int j = 0; j < 8; ++j) { float d = acc[i][j] - mu; q += d * d; }
#pragma unroll
            for (int o = 1; o < 16; o <<= 1) q += __shfl_xor_sync(0xffffffffu, q, o);
            float rs = rsqrtf(q * (1.f / 128.f) + LN_EPS);
#pragma unroll
            for (int j = 0; j < 8; ++j)
                acc[i][j] = fmaxf((acc[i][j] - mu) * rs * gv[j] + b2[j], 0.f);
        }
    }
#pragma unroll
    for (int i = 0; i < 8; ++i) {
        int row = row0 + (i < 4 ? ty * 4 + i : 64 + ty * 4 + i - 4);
        if (row < n) {
            float4 o0 = make_float4(acc[i][0], acc[i][1], acc[i][2], acc[i][3]);
            float4 o1 = make_float4(acc[i][4], acc[i][5], acc[i][6], acc[i][7]);
            *(float4*)&C[(size_t)row * OUT + col0 + tx * 4]      = o0;
            *(float4*)&C[(size_t)row * OUT + col0 + 64 + tx * 4] = o1;
        }
    }
}

// ---------------- fused per-destination prop kernel (single-pass online softmax) ----
// Warp per dst node. Src indices are prefetched one-per-lane per 32-edge chunk
// and broadcast via shfl, removing the dependent index load from the per-edge
// chain. __expf (MUFU.EX2) replaces libm expf.
__global__ void k_prop(const float* __restrict__ f, const float* __restrict__ x,
                       const float* __restrict__ yin, const float* __restrict__ attn,
                       const int* __restrict__ offp, const int* __restrict__ sp,
                       const int* __restrict__ offs2, const int* __restrict__ ss,
                       const void* __restrict__ flag,
                       float* __restrict__ hout, float* __restrict__ yout) {
    int v = blockIdx.x * 8 + (threadIdx.x >> 5);
    if (v >= NN) return;
    int lane = threadIdx.x & 31;

    float4 at = *(const float4*)&attn[lane * 4];
    float4 fv = *(const float4*)&f[(size_t)v * HD + lane * 4];

    float4 tf  = make_float4(0.f, 0.f, 0.f, 0.f);
    float4 ty0 = make_float4(0.f, 0.f, 0.f, 0.f);
    float4 ty1 = make_float4(0.f, 0.f, 0.f, 0.f);

#pragma unroll
    for (int rel = 0; rel < 2; ++rel) {
        const int* off  = rel ? offs2 : offp;
        const int* ssrc = rel ? ss    : sp;
        int lo = off[v], hi = off[v + 1];

        float m   = -__int_as_float(0x7f800000);
        float den = 0.f;
        float4 af  = make_float4(0.f, 0.f, 0.f, 0.f);
        float4 ay0 = make_float4(0.f, 0.f, 0.f, 0.f);
        float4 ay1 = make_float4(0.f, 0.f, 0.f, 0.f);

        for (int base = lo; base < hi; base += 32) {
            int j = base + lane;
            int myu = (j < hi) ? __ldg(&ssrc[j]) : 0;
            int cnt = min(32, hi - base);
#pragma unroll 2
            for (int t = 0; t < cnt; ++t) {
                int u = __shfl_sync(0xffffffffu, myu, t);
                float4 fu = *(const float4*)&f[(size_t)u * HD + lane * 4];
                float4 y0 = *(const float4*)&yin[(size_t)u * OD + lane * 4];
                float4 y1 = *(const float4*)&yin[(size_t)u * OD + 128 + lane * 4];
                float p = lrelu02(fu.x + fv.x) * at.x
                        + lrelu02(fu.y + fv.y) * at.y
                        + lrelu02(fu.z + fv.z) * at.z
                        + lrelu02(fu.w + fv.w) * at.w;
#pragma unroll
                for (int o = 16; o; o >>= 1) p += __shfl_xor_sync(0xffffffffu, p, o);
                if (p > m) {
                    float r = __expf(m - p);   // 0 on first edge (m = -inf)
                    den *= r;
                    af.x *= r;  af.y *= r;  af.z *= r;  af.w *= r;
                    ay0.x *= r; ay0.y *= r; ay0.z *= r; ay0.w *= r;
                    ay1.x *= r; ay1.y *= r; ay1.z *= r; ay1.w *= r;
                    m = p;
                }
                float w = __expf(p - m);
                den += w;
                af.x = fmaf(fu.x, w, af.x);
                af.y = fmaf(fu.y, w, af.y);
                af.z = fmaf(fu.z, w, af.z);
                af.w = fmaf(fu.w, w, af.w);
                ay0.x = fmaf(y0.x, w, ay0.x); ay0.y = fmaf(y0.y, w, ay0.y);
                ay0.z = fmaf(y0.z, w, ay0.z); ay0.w = fmaf(y0.w, w, ay0.w);
                ay1.x = fmaf(y1.x, w, ay1.x); ay1.y = fmaf(y1.y, w, ay1.y);
                ay1.z = fmaf(y1.z, w, ay1.z); ay1.w = fmaf(y1.w, w, ay1.w);
            }
        }
        float rden = (den > 0.f) ? 1.f / den : 0.f;
        tf.x  = fmaf(af.x,  rden, tf.x);  tf.y  = fmaf(af.y,  rden, tf.y);
        tf.z  = fmaf(af.z,  rden, tf.z);  tf.w  = fmaf(af.w,  rden, tf.w);
        ty0.x = fmaf(ay0.x, rden, ty0.x); ty0.y = fmaf(ay0.y, rden, ty0.y);
        ty0.z = fmaf(ay0.z, rden, ty0.z); ty0.w = fmaf(ay0.w, rden, ty0.w);
        ty1.x = fmaf(ay1.x, rden, ty1.x); ty1.y = fmaf(ay1.y, rden, ty1.y);
        ty1.z = fmaf(ay1.z, rden, ty1.z); ty1.w = fmaf(ay1.w, rden, ty1.w);
    }

    // h epilogue: elu(agg_p + agg_s + 2*x)
    float4 xv = *(const float4*)&x[(size_t)v * HD + lane * 4];
    float4 h;
    h.x = tf.x + 2.f * xv.x; h.x = h.x > 0.f ? h.x : expm1f(h.x);
    h.y = tf.y + 2.f * xv.y; h.y = h.y > 0.f ? h.y : expm1f(h.y);
    h.z = tf.z + 2.f * xv.z; h.z = h.z > 0.f ? h.z : expm1f(h.z);
    h.w = tf.w + 2.f * xv.w; h.w = h.w > 0.f ? h.w : expm1f(h.w);
    *(float4*)&hout[(size_t)v * HD + lane * 4] = h;

    // y epilogue: normalize or copy per flag
    float q = ty0.x * ty0.x + ty0.y * ty0.y + ty0.z * ty0.z + ty0.w * ty0.w
            + ty1.x * ty1.x + ty1.y * ty1.y + ty1.z * ty1.z + ty1.w * ty1.w;
#pragma unroll
    for (int o = 16; o; o >>= 1) q += __shfl_xor_sync(0xffffffffu, q, o);
    float inv = 1.f / fmaxf(sqrtf(q), 1e-12f);
    bool fl;
    if (g_flagIsInt) fl = ((const int*)flag)[v] != 0;
    else             fl = ((const unsigned char*)flag)[v] != 0;
    size_t base = (size_t)v * OD + lane * 4;
    float4 r0, r1;
    if (fl) {
        r0 = *(const float4*)&yin[base];
        r1 = *(const float4*)&yin[base + 128];
    } else {
        r0 = make_float4(ty0.x * inv, ty0.y * inv, ty0.z * inv, ty0.w * inv);
        r1 = make_float4(ty1.x * inv, ty1.y * inv, ty1.z * inv, ty1.w * inv);
    }
    *(float4*)&yout[base]       = r0;
    *(float4*)&yout[base + 128] = r1;
}

// ---------------- host orchestration ----------------
extern "C" void kernel_launch(void* const* d_in, const int* in_sizes, int n_in,
                              void* d_out, int out_size) {
    const int*   emb_indices = (const int*)  d_in[0];
    const int*   emb_offsets = (const int*)  d_in[1];
    const float* emb_weights = (const float*)d_in[2];
    const float* y           = (const float*)d_in[3];
    const void*  flag        = d_in[4];
    const int* src_p1 = (const int*)d_in[5];
    const int* dst_p1 = (const int*)d_in[6];
    const int* src_s1 = (const int*)d_in[7];
    const int* dst_s1 = (const int*)d_in[8];
    const int* src_p2 = (const int*)d_in[9];
    const int* dst_p2 = (const int*)d_in[10];
    const int* src_s2 = (const int*)d_in[11];
    const int* dst_s2 = (const int*)d_in[12];
    const float* embed_W = (const float*)d_in[13];
    const float* embed_b = (const float*)d_in[14];
    const float* mlp_W1  = (const float*)d_in[15];
    const float* mlp_b1  = (const float*)d_in[16];
    const float* ln1_g   = (const float*)d_in[17];
    const float* ln1_b   = (const float*)d_in[18];
    const float* mlp_W2  = (const float*)d_in[19];
    const float* mlp_b2  = (const float*)d_in[20];
    const float* ln2_g   = (const float*)d_in[21];
    const float* ln2_b   = (const float*)d_in[22];
    const float* Wsrc1   = (const float*)d_in[23];
    const float* bsrc1   = (const float*)d_in[24];
    const float* attn1   = (const float*)d_in[25];
    const float* Wsrc2   = (const float*)d_in[26];
    const float* bsrc2   = (const float*)d_in[27];
    const float* attn2   = (const float*)d_in[28];
    const float* out_W   = (const float*)d_in[29];
    const float* out_b   = (const float*)d_in[30];

    float *hA, *hB, *f, *yA;
    int *off, *ssrc, *cnt, *cur;
    cudaGetSymbolAddress((void**)&hA,   g_hA);
    cudaGetSymbolAddress((void**)&hB,   g_hB);
    cudaGetSymbolAddress((void**)&f,    g_f);
    cudaGetSymbolAddress((void**)&yA,   g_yA);
    cudaGetSymbolAddress((void**)&off,  g_off);
    cudaGetSymbolAddress((void**)&ssrc, g_ssrc);
    cudaGetSymbolAddress((void**)&cnt,  g_cnt);
    cudaGetSymbolAddress((void**)&cur,  g_cur);

    float* logits = (float*)d_out;
    float* yh_out = (float*)d_out + (size_t)NN * OD;

    k_detect_flag<<<1, 256>>>((const unsigned char*)flag);

    // ---- CSR sorts (dst-sorted edge lists) for the 4 relations ----
    cudaMemsetAsync(cnt, 0, sizeof(int) * 4 * NN);
    dim3 ge((NE + 255) / 256, 4);
    k_hist4<<<ge, 256>>>(dst_p1, dst_s1, dst_p2, dst_s2, cnt);
    k_scan4<<<4, 1024>>>(cnt, off, cur);
    k_scatter4<<<ge, 256>>>(src_p1, dst_p1, src_s1, dst_s1,
                            src_p2, dst_p2, src_s2, dst_s2, cur, ssrc);

    // ---- EmbeddingBag + MLP (LN fused into GEMM epilogue) ----
    k_embed<<<(NN + 7) / 8, 256>>>(emb_indices, emb_offsets, emb_weights, embed_W, embed_b, hA);
    dim3 g1((NN + 127) / 128, 1);
    k_gemm<<<g1, 256>>>(hA, mlp_W1, mlp_b1, ln1_g, ln1_b, hB, NN, 128, 1);
    k_gemm<<<g1, 256>>>(hB, mlp_W2, mlp_b2, ln2_g, ln2_b, hA, NN, 128, 1);

    // ---- prop 1: x = hA -> hB, y -> yA ----
    k_gemm<<<g1, 256>>>(hA, Wsrc1, bsrc1, nullptr, nullptr, f, NN, 128, 0);
    k_prop<<<(NN + 7) / 8, 256>>>(f, hA, y, attn1,
                                  off + 0 * (NN + 1), ssrc + 0 * NE,
                                  off + 1 * (NN + 1), ssrc + 1 * NE,
                                  flag, hB, yA);

    // ---- prop 2: x = hB -> hA, yA -> yh_out ----
    k_gemm<<<g1, 256>>>(hB, Wsrc2, bsrc2, nullptr, nullptr, f, NN, 128, 0);
    k_prop<<<(NN + 7) / 8, 256>>>(f, hB, yA, attn2,
                                  off + 2 * (NN + 1), ssrc + 2 * NE,
                                  off + 3 * (NN + 1), ssrc + 3 * NE,
                                  flag, hA, yh_out);

    // ---- logits = h @ out_W + out_b ----
    dim3 g2((NN + 127) / 128, 2);
    k_gemm<<<g2, 256>>>(hA, out_W, out_b, nullptr, nullptr, logits, NN, 256, 0);
}

// round 8
// speedup vs baseline: 2.6928x; 1.0112x over previous
#include <cuda_runtime.h>
#include <math.h>

#define NN 50000
#define HD 128
#define OD 256
#define NE 800000
#define LN_EPS 1e-5f

// ---------------- scratch (static device globals; no allocation) ----------------
__device__ float g_hA[NN * HD];
__device__ float g_hB[NN * HD];
__device__ float g_f [NN * HD];
__device__ float g_yA [NN * OD];
__device__ int   g_off [4][NN + 1];
__device__ int   g_ssrc[4][NE];
__device__ int   g_cnt[4][NN];
__device__ int   g_cur[4][NN];
__device__ int   g_flagIsInt;

// ---------------- helpers ----------------
__device__ __forceinline__ float lrelu02(float x) {
    return x >= 0.f ? x : 0.2f * x;
}

__device__ __forceinline__ unsigned long long pack2(float lo, float hi) {
    unsigned long long r;
    asm("mov.b64 %0, {%1, %2};" : "=l"(r) : "f"(lo), "f"(hi));
    return r;
}

__device__ __forceinline__ unsigned long long fma2(unsigned long long a,
                                                   unsigned long long b,
                                                   unsigned long long c) {
    unsigned long long d;
    asm("fma.rn.f32x2 %0, %1, %2, %3;" : "=l"(d) : "l"(a), "l"(b), "l"(c));
    return d;
}

// ---------------- kernels ----------------

// Detect flag buffer layout: int32 (bytes 1..3 of each word are 0) vs uint8.
__global__ void k_detect_flag(const unsigned char* __restrict__ flag) {
    __shared__ int cnt;
    if (threadIdx.x == 0) cnt = 0;
    __syncthreads();
    int local = 0;
    for (int i = threadIdx.x; i < 4000; i += 256)
        if ((i & 3) != 0 && flag[i] != 0) local = 1;
    if (local) atomicOr(&cnt, 1);
    __syncthreads();
    if (threadIdx.x == 0) g_flagIsInt = (cnt == 0) ? 1 : 0;
}

// -------- counting sort by dst (all 4 relations in one grid via blockIdx.y) --------
__global__ void k_hist4(const int* __restrict__ d0, const int* __restrict__ d1,
                        const int* __restrict__ d2, const int* __restrict__ d3,
                        int* __restrict__ cnt) {
    int e = blockIdx.x * 256 + threadIdx.x;
    int r = blockIdx.y;
    const int* dst = r == 0 ? d0 : r == 1 ? d1 : r == 2 ? d2 : d3;
    if (e < NE) atomicAdd(&cnt[r * NN + dst[e]], 1);
}

// 4 blocks, one relation each: exclusive scan -> offs[NN+1], cur[NN]
__global__ void k_scan4(const int* __restrict__ cntAll, int* __restrict__ offsAll,
                        int* __restrict__ curAll) {
    __shared__ int part[1024];
    const int CH = (NN + 1023) / 1024;
    int r = blockIdx.x;
    const int* cnt = cntAll + r * NN;
    int* offs = offsAll + r * (NN + 1);
    int* cur  = curAll  + r * NN;
    int t = threadIdx.x;
    int lo = t * CH, hi = min(lo + CH, NN);
    int s = 0;
    for (int i = lo; i < hi; ++i) s += cnt[i];
    part[t] = s;
    __syncthreads();
    for (int o = 1; o < 1024; o <<= 1) {
        int v = (t >= o) ? part[t - o] : 0;
        __syncthreads();
        part[t] += v;
        __syncthreads();
    }
    int base = (t == 0) ? 0 : part[t - 1];
    for (int i = lo; i < hi; ++i) {
        offs[i] = base;
        cur[i]  = base;
        base += cnt[i];
    }
    if (t == 1023) offs[NN] = base;
}

__global__ void k_scatter4(const int* __restrict__ s0, const int* __restrict__ d0,
                           const int* __restrict__ s1, const int* __restrict__ d1,
                           const int* __restrict__ s2, const int* __restrict__ d2,
                           const int* __restrict__ s3, const int* __restrict__ d3,
                           int* __restrict__ cur, int* __restrict__ ssrc) {
    int e = blockIdx.x * 256 + threadIdx.x;
    int r = blockIdx.y;
    const int* src = r == 0 ? s0 : r == 1 ? s1 : r == 2 ? s2 : s3;
    const int* dst = r == 0 ? d0 : r == 1 ? d1 : r == 2 ? d2 : d3;
    if (e < NE) {
        int v = dst[e];
        int pos = atomicAdd(&cur[r * NN + v], 1);
        ssrc[r * NE + pos] = src[e];
    }
}

// EmbeddingBag(sum, per_sample_weights) + bias + relu. Warp per node.
__global__ void k_embed(const int* __restrict__ idx, const int* __restrict__ offs,
                        const float* __restrict__ wts, const float* __restrict__ table,
                        const float* __restrict__ bias, float* __restrict__ out) {
    int n = blockIdx.x * 8 + (threadIdx.x >> 5);
    if (n >= NN) return;
    int lane = threadIdx.x & 31;
    int s = offs[n], e = offs[n + 1];
    float4 acc = make_float4(0.f, 0.f, 0.f, 0.f);
    for (int base = s; base < e; base += 32) {
        int j = base + lane;
        int id = (j < e) ? idx[j] : 0;
        float w = (j < e) ? wts[j] : 0.f;
        int cnt = min(32, e - base);
#pragma unroll 2
        for (int t = 0; t < cnt; ++t) {
            int   uj = __shfl_sync(0xffffffffu, id, t);
            float wj = __shfl_sync(0xffffffffu, w,  t);
            float4 tv = *(const float4*)&table[(size_t)uj * HD + lane * 4];
            acc.x = fmaf(tv.x, wj, acc.x);
            acc.y = fmaf(tv.y, wj, acc.y);
            acc.z = fmaf(tv.z, wj, acc.z);
            acc.w = fmaf(tv.w, wj, acc.w);
        }
    }
    float4 b4 = *(const float4*)&bias[lane * 4];
    float4 r;
    r.x = fmaxf(acc.x + b4.x, 0.f);
    r.y = fmaxf(acc.y + b4.y, 0.f);
    r.z = fmaxf(acc.z + b4.z, 0.f);
    r.w = fmaxf(acc.w + b4.w, 0.f);
    *(float4*)&out[(size_t)n * HD + lane * 4] = r;
}

// C[n,OUT] = X[n,128] @ W[128,OUT] + Bias, optionally fused LayerNorm(128)+ReLU.
// 128x128 tile, 256 threads, 8x8 accum per thread held as 8x4 packed f32x2,
// inner loop uses fma.rn.f32x2 (FFMA2) for 2x FMA-pipe throughput.
__global__ __launch_bounds__(256, 2)
void k_gemm(const float* __restrict__ X, const float* __restrict__ W,
            const float* __restrict__ Bias, const float* __restrict__ lng,
            const float* __restrict__ lnb, float* __restrict__ C,
            int n, int OUT, int do_ln) {
    __shared__ float xs[32][132];
    __shared__ float ws[32][132];
    int row0 = blockIdx.x * 128, col0 = blockIdx.y * 128;
    int tid = threadIdx.x;
    int tx = tid & 15, ty = tid >> 4;
    unsigned long long acc2[8][4] = {};   // packed (f32,f32) pairs, 0ull == (0.f,0.f)
    for (int kb = 0; kb < 128; kb += 32) {
#pragma unroll
        for (int it = 0; it < 4; ++it) {
            int idx = it * 256 + tid;
            int m = idx >> 3, kq = (idx & 7) * 4;
            int row = row0 + m;
            float4 v = (row < n) ? *(const float4*)&X[(size_t)row * 128 + kb + kq]
                                 : make_float4(0.f, 0.f, 0.f, 0.f);
            xs[kq + 0][m] = v.x; xs[kq + 1][m] = v.y;
            xs[kq + 2][m] = v.z; xs[kq + 3][m] = v.w;
        }
#pragma unroll
        for (int it = 0; it < 4; ++it) {
            int idx = it * 256 + tid;
            int k = idx >> 5, cq = (idx & 31) * 4;
            *(float4*)&ws[k][cq] = *(const float4*)&W[(size_t)(kb + k) * OUT + col0 + cq];
        }
        __syncthreads();
#pragma unroll
        for (int k = 0; k < 32; ++k) {
            float4 a0 = *(const float4*)&xs[k][ty * 4];
            float4 a1 = *(const float4*)&xs[k][64 + ty * 4];
            const unsigned long long* bp0 = (const unsigned long long*)&ws[k][tx * 4];
            const unsigned long long* bp1 = (const unsigned long long*)&ws[k][64 + tx * 4];
            unsigned long long b01 = bp0[0], b23 = bp0[1];
            unsigned long long b45 = bp1[0], b67 = bp1[1];
            float av[8] = {a0.x, a0.y, a0.z, a0.w, a1.x, a1.y, a1.z, a1.w};
#pragma unroll
            for (int i = 0; i < 8; ++i) {
                unsigned long long aa = pack2(av[i], av[i]);
                acc2[i][0] = fma2(aa, b01, acc2[i][0]);
                acc2[i][1] = fma2(aa, b23, acc2[i][1]);
                acc2[i][2] = fma2(aa, b45, acc2[i][2]);
                acc2[i][3] = fma2(aa, b67, acc2[i][3]);
            }
        }
        __syncthreads();
    }
    // unpack accumulators
    float acc[8][8];
#pragma unroll
    for (int i = 0; i < 8; ++i)
#pragma unroll
        for (int q = 0; q < 4; ++q)
            asm("mov.b64 {%0, %1}, %2;"
                : "=f"(acc[i][q * 2]), "=f"(acc[i][q * 2 + 1]) : "l"(acc2[i][q]));

    // bias add
    float pb[8];
#pragma unroll
    for (int j = 0; j < 8; ++j) {
        int col = col0 + (j < 4 ? tx * 4 + j : 64 + tx * 4 + j - 4);
        pb[j] = Bias[col];
    }
#pragma unroll
    for (int i = 0; i < 8; ++i)
#pragma unroll
        for (int j = 0; j < 8; ++j) acc[i][j] += pb[j];

    if (do_ln) {  // OUT must be 128: block holds the entire row
        float gv[8], b2[8];
#pragma unroll
        for (int j = 0; j < 8; ++j) {
            int col = (j < 4 ? tx * 4 + j : 64 + tx * 4 + j - 4);
            gv[j] = lng[col]; b2[j] = lnb[col];
        }
#pragma unroll
        for (int i = 0; i < 8; ++i) {
            float s = 0.f;
#pragma unroll
            for (int j = 0; j < 8; ++j) s += acc[i][j];
#pragma unroll
            for (int o = 1; o < 16; o <<= 1) s += __shfl_xor_sync(0xffffffffu, s, o);
            float mu = s * (1.f / 128.f);
            float q = 0.f;
#pragma unroll
            for (int j = 0; j < 8; ++j) { float d = acc[i][j] - mu; q += d * d; }
#pragma unroll
            for (int o = 1; o < 16; o <<= 1) q += __shfl_xor_sync(0xffffffffu, q, o);
            float rs = rsqrtf(q * (1.f / 128.f) + LN_EPS);
#pragma unroll
            for (int j = 0; j < 8; ++j)
                acc[i][j] = fmaxf((acc[i][j] - mu) * rs * gv[j] + b2[j], 0.f);
        }
    }
#pragma unroll
    for (int i = 0; i < 8; ++i) {
        int row = row0 + (i < 4 ? ty * 4 + i : 64 + ty * 4 + i - 4);
        if (row < n) {
            float4 o0 = make_float4(acc[i][0], acc[i][1], acc[i][2], acc[i][3]);
            float4 o1 = make_float4(acc[i][4], acc[i][5], acc[i][6], acc[i][7]);
            *(float4*)&C[(size_t)row * OUT + col0 + tx * 4]      = o0;
            *(float4*)&C[(size_t)row * OUT + col0 + 64 + tx * 4] = o1;
        }
    }
}

// ---------------- fused per-destination prop kernel (single-pass online softmax) ----
__global__ void k_prop(const float* __restrict__ f, const float* __restrict__ x,
                       const float* __restrict__ yin, const float* __restrict__ attn,
                       const int* __restrict__ offp, const int* __restrict__ sp,
                       const int* __restrict__ offs2, const int* __restrict__ ss,
                       const void* __restrict__ flag,
                       float* __restrict__ hout, float* __restrict__ yout) {
    int v = blockIdx.x * 8 + (threadIdx.x >> 5);
    if (v >= NN) return;
    int lane = threadIdx.x & 31;

    float4 at = *(const float4*)&attn[lane * 4];
    float4 fv = *(const float4*)&f[(size_t)v * HD + lane * 4];

    float4 tf  = make_float4(0.f, 0.f, 0.f, 0.f);
    float4 ty0 = make_float4(0.f, 0.f, 0.f, 0.f);
    float4 ty1 = make_float4(0.f, 0.f, 0.f, 0.f);

#pragma unroll
    for (int rel = 0; rel < 2; ++rel) {
        const int* off  = rel ? offs2 : offp;
        const int* ssrc = rel ? ss    : sp;
        int lo = off[v], hi = off[v + 1];

        float m   = -__int_as_float(0x7f800000);
        float den = 0.f;
        float4 af  = make_float4(0.f, 0.f, 0.f, 0.f);
        float4 ay0 = make_float4(0.f, 0.f, 0.f, 0.f);
        float4 ay1 = make_float4(0.f, 0.f, 0.f, 0.f);

        for (int base = lo; base < hi; base += 32) {
            int j = base + lane;
            int myu = (j < hi) ? __ldg(&ssrc[j]) : 0;
            int cnt = min(32, hi - base);
#pragma unroll 2
            for (int t = 0; t < cnt; ++t) {
                int u = __shfl_sync(0xffffffffu, myu, t);
                float4 fu = *(const float4*)&f[(size_t)u * HD + lane * 4];
                float4 y0 = *(const float4*)&yin[(size_t)u * OD + lane * 4];
                float4 y1 = *(const float4*)&yin[(size_t)u * OD + 128 + lane * 4];
                float p = lrelu02(fu.x + fv.x) * at.x
                        + lrelu02(fu.y + fv.y) * at.y
                        + lrelu02(fu.z + fv.z) * at.z
                        + lrelu02(fu.w + fv.w) * at.w;
#pragma unroll
                for (int o = 16; o; o >>= 1) p += __shfl_xor_sync(0xffffffffu, p, o);
                if (p > m) {
                    float r = __expf(m - p);   // 0 on first edge (m = -inf)
                    den *= r;
                    af.x *= r;  af.y *= r;  af.z *= r;  af.w *= r;
                    ay0.x *= r; ay0.y *= r; ay0.z *= r; ay0.w *= r;
                    ay1.x *= r; ay1.y *= r; ay1.z *= r; ay1.w *= r;
                    m = p;
                }
                float w = __expf(p - m);
                den += w;
                af.x = fmaf(fu.x, w, af.x);
                af.y = fmaf(fu.y, w, af.y);
                af.z = fmaf(fu.z, w, af.z);
                af.w = fmaf(fu.w, w, af.w);
                ay0.x = fmaf(y0.x, w, ay0.x); ay0.y = fmaf(y0.y, w, ay0.y);
                ay0.z = fmaf(y0.z, w, ay0.z); ay0.w = fmaf(y0.w, w, ay0.w);
                ay1.x = fmaf(y1.x, w, ay1.x); ay1.y = fmaf(y1.y, w, ay1.y);
                ay1.z = fmaf(y1.z, w, ay1.z); ay1.w = fmaf(y1.w, w, ay1.w);
            }
        }
        float rden = (den > 0.f) ? 1.f / den : 0.f;
        tf.x  = fmaf(af.x,  rden, tf.x);  tf.y  = fmaf(af.y,  rden, tf.y);
        tf.z  = fmaf(af.z,  rden, tf.z);  tf.w  = fmaf(af.w,  rden, tf.w);
        ty0.x = fmaf(ay0.x, rden, ty0.x); ty0.y = fmaf(ay0.y, rden, ty0.y);
        ty0.z = fmaf(ay0.z, rden, ty0.z); ty0.w = fmaf(ay0.w, rden, ty0.w);
        ty1.x = fmaf(ay1.x, rden, ty1.x); ty1.y = fmaf(ay1.y, rden, ty1.y);
        ty1.z = fmaf(ay1.z, rden, ty1.z); ty1.w = fmaf(ay1.w, rden, ty1.w);
    }

    // h epilogue: elu(agg_p + agg_s + 2*x)
    float4 xv = *(const float4*)&x[(size_t)v * HD + lane * 4];
    float4 h;
    h.x = tf.x + 2.f * xv.x; h.x = h.x > 0.f ? h.x : expm1f(h.x);
    h.y = tf.y + 2.f * xv.y; h.y = h.y > 0.f ? h.y : expm1f(h.y);
    h.z = tf.z + 2.f * xv.z; h.z = h.z > 0.f ? h.z : expm1f(h.z);
    h.w = tf.w + 2.f * xv.w; h.w = h.w > 0.f ? h.w : expm1f(h.w);
    *(float4*)&hout[(size_t)v * HD + lane * 4] = h;

    // y epilogue: normalize or copy per flag
    float q = ty0.x * ty0.x + ty0.y * ty0.y + ty0.z * ty0.z + ty0.w * ty0.w
            + ty1.x * ty1.x + ty1.y * ty1.y + ty1.z * ty1.z + ty1.w * ty1.w;
#pragma unroll
    for (int o = 16; o; o >>= 1) q += __shfl_xor_sync(0xffffffffu, q, o);
    float inv = 1.f / fmaxf(sqrtf(q), 1e-12f);
    bool fl;
    if (g_flagIsInt) fl = ((const int*)flag)[v] != 0;
    else             fl = ((const unsigned char*)flag)[v] != 0;
    size_t base = (size_t)v * OD + lane * 4;
    float4 r0, r1;
    if (fl) {
        r0 = *(const float4*)&yin[base];
        r1 = *(const float4*)&yin[base + 128];
    } else {
        r0 = make_float4(ty0.x * inv, ty0.y * inv, ty0.z * inv, ty0.w * inv);
        r1 = make_float4(ty1.x * inv, ty1.y * inv, ty1.z * inv, ty1.w * inv);
    }
    *(float4*)&yout[base]       = r0;
    *(float4*)&yout[base + 128] = r1;
}

// ---------------- host orchestration ----------------
extern "C" void kernel_launch(void* const* d_in, const int* in_sizes, int n_in,
                              void* d_out, int out_size) {
    const int*   emb_indices = (const int*)  d_in[0];
    const int*   emb_offsets = (const int*)  d_in[1];
    const float* emb_weights = (const float*)d_in[2];
    const float* y           = (const float*)d_in[3];
    const void*  flag        = d_in[4];
    const int* src_p1 = (const int*)d_in[5];
    const int* dst_p1 = (const int*)d_in[6];
    const int* src_s1 = (const int*)d_in[7];
    const int* dst_s1 = (const int*)d_in[8];
    const int* src_p2 = (const int*)d_in[9];
    const int* dst_p2 = (const int*)d_in[10];
    const int* src_s2 = (const int*)d_in[11];
    const int* dst_s2 = (const int*)d_in[12];
    const float* embed_W = (const float*)d_in[13];
    const float* embed_b = (const float*)d_in[14];
    const float* mlp_W1  = (const float*)d_in[15];
    const float* mlp_b1  = (const float*)d_in[16];
    const float* ln1_g   = (const float*)d_in[17];
    const float* ln1_b   = (const float*)d_in[18];
    const float* mlp_W2  = (const float*)d_in[19];
    const float* mlp_b2  = (const float*)d_in[20];
    const float* ln2_g   = (const float*)d_in[21];
    const float* ln2_b   = (const float*)d_in[22];
    const float* Wsrc1   = (const float*)d_in[23];
    const float* bsrc1   = (const float*)d_in[24];
    const float* attn1   = (const float*)d_in[25];
    const float* Wsrc2   = (const float*)d_in[26];
    const float* bsrc2   = (const float*)d_in[27];
    const float* attn2   = (const float*)d_in[28];
    const float* out_W   = (const float*)d_in[29];
    const float* out_b   = (const float*)d_in[30];

    float *hA, *hB, *f, *yA;
    int *off, *ssrc, *cnt, *cur;
    cudaGetSymbolAddress((void**)&hA,   g_hA);
    cudaGetSymbolAddress((void**)&hB,   g_hB);
    cudaGetSymbolAddress((void**)&f,    g_f);
    cudaGetSymbolAddress((void**)&yA,   g_yA);
    cudaGetSymbolAddress((void**)&off,  g_off);
    cudaGetSymbolAddress((void**)&ssrc, g_ssrc);
    cudaGetSymbolAddress((void**)&cnt,  g_cnt);
    cudaGetSymbolAddress((void**)&cur,  g_cur);

    float* logits = (float*)d_out;
    float* yh_out = (float*)d_out + (size_t)NN * OD;

    k_detect_flag<<<1, 256>>>((const unsigned char*)flag);

    // ---- CSR sorts (dst-sorted edge lists) for the 4 relations ----
    cudaMemsetAsync(cnt, 0, sizeof(int) * 4 * NN);
    dim3 ge((NE + 255) / 256, 4);
    k_hist4<<<ge, 256>>>(dst_p1, dst_s1, dst_p2, dst_s2, cnt);
    k_scan4<<<4, 1024>>>(cnt, off, cur);
    k_scatter4<<<ge, 256>>>(src_p1, dst_p1, src_s1, dst_s1,
                            src_p2, dst_p2, src_s2, dst_s2, cur, ssrc);

    // ---- EmbeddingBag + MLP (LN fused into GEMM epilogue) ----
    k_embed<<<(NN + 7) / 8, 256>>>(emb_indices, emb_offsets, emb_weights, embed_W, embed_b, hA);
    dim3 g1((NN + 127) / 128, 1);
    k_gemm<<<g1, 256>>>(hA, mlp_W1, mlp_b1, ln1_g, ln1_b, hB, NN, 128, 1);
    k_gemm<<<g1, 256>>>(hB, mlp_W2, mlp_b2, ln2_g, ln2_b, hA, NN, 128, 1);

    // ---- prop 1: x = hA -> hB, y -> yA ----
    k_gemm<<<g1, 256>>>(hA, Wsrc1, bsrc1, nullptr, nullptr, f, NN, 128, 0);
    k_prop<<<(NN + 7) / 8, 256>>>(f, hA, y, attn1,
                                  off + 0 * (NN + 1), ssrc + 0 * NE,
                                  off + 1 * (NN + 1), ssrc + 1 * NE,
                                  flag, hB, yA);

    // ---- prop 2: x = hB -> hA, yA -> yh_out ----
    k_gemm<<<g1, 256>>>(hB, Wsrc2, bsrc2, nullptr, nullptr, f, NN, 128, 0);
    k_prop<<<(NN + 7) / 8, 256>>>(f, hB, yA, attn2,
                                  off + 2 * (NN + 1), ssrc + 2 * NE,
                                  off + 3 * (NN + 1), ssrc + 3 * NE,
                                  flag, hA, yh_out);

    // ---- logits = h @ out_W + out_b ----
    dim3 g2((NN + 127) / 128, 2);
    k_gemm<<<g2, 256>>>(hA, out_W, out_b, nullptr, nullptr, logits, NN, 256, 0);
}

// round 9
// speedup vs baseline: 2.9099x; 1.0806x over previous
#include <cuda_runtime.h>
#include <math.h>

#define NN 50000
#define HD 128
#define OD 256
#define NE 800000
#define LN_EPS 1e-5f

typedef unsigned long long u64;

// ---------------- scratch (static device globals; no allocation) ----------------
__device__ float g_hA[NN * HD];
__device__ float g_hB[NN * HD];
__device__ float g_f [NN * HD];
__device__ float g_yA [NN * OD];
__device__ int   g_off [4][NN + 1];
__device__ int   g_ssrc[4][NE];
__device__ int   g_cnt[4][NN];
__device__ int   g_cur[4][NN];
__device__ int   g_flagIsInt;

// ---------------- helpers ----------------
__device__ __forceinline__ u64 pack2(float lo, float hi) {
    u64 r;
    asm("mov.b64 %0, {%1, %2};" : "=l"(r) : "f"(lo), "f"(hi));
    return r;
}
__device__ __forceinline__ void unpack2(u64 v, float& lo, float& hi) {
    asm("mov.b64 {%0, %1}, %2;" : "=f"(lo), "=f"(hi) : "l"(v));
}
__device__ __forceinline__ u64 fma2(u64 a, u64 b, u64 c) {
    u64 d;
    asm("fma.rn.f32x2 %0, %1, %2, %3;" : "=l"(d) : "l"(a), "l"(b), "l"(c));
    return d;
}
__device__ __forceinline__ u64 mul2(u64 a, u64 b) {
    u64 d;
    asm("mul.rn.f32x2 %0, %1, %2;" : "=l"(d) : "l"(a), "l"(b));
    return d;
}
__device__ __forceinline__ u64 add2(u64 a, u64 b) {
    u64 d;
    asm("add.rn.f32x2 %0, %1, %2;" : "=l"(d) : "l"(a), "l"(b));
    return d;
}
__device__ __forceinline__ u64 abs2(u64 a) {
    return a & 0x7FFFFFFF7FFFFFFFULL;
}

// ---------------- kernels ----------------

// Detect flag buffer layout: int32 (bytes 1..3 of each word are 0) vs uint8.
__global__ void k_detect_flag(const unsigned char* __restrict__ flag) {
    __shared__ int cnt;
    if (threadIdx.x == 0) cnt = 0;
    __syncthreads();
    int local = 0;
    for (int i = threadIdx.x; i < 4000; i += 256)
        if ((i & 3) != 0 && flag[i] != 0) local = 1;
    if (local) atomicOr(&cnt, 1);
    __syncthreads();
    if (threadIdx.x == 0) g_flagIsInt = (cnt == 0) ? 1 : 0;
}

// -------- counting sort by dst (all 4 relations in one grid via blockIdx.y) --------
__global__ void k_hist4(const int* __restrict__ d0, const int* __restrict__ d1,
                        const int* __restrict__ d2, const int* __restrict__ d3,
                        int* __restrict__ cnt) {
    int e = blockIdx.x * 256 + threadIdx.x;
    int r = blockIdx.y;
    const int* dst = r == 0 ? d0 : r == 1 ? d1 : r == 2 ? d2 : d3;
    if (e < NE) atomicAdd(&cnt[r * NN + dst[e]], 1);
}

// 4 blocks, one relation each: exclusive scan -> offs[NN+1], cur[NN]
__global__ void k_scan4(const int* __restrict__ cntAll, int* __restrict__ offsAll,
                        int* __restrict__ curAll) {
    __shared__ int part[1024];
    const int CH = (NN + 1023) / 1024;
    int r = blockIdx.x;
    const int* cnt = cntAll + r * NN;
    int* offs = offsAll + r * (NN + 1);
    int* cur  = curAll  + r * NN;
    int t = threadIdx.x;
    int lo = t * CH, hi = min(lo + CH, NN);
    int s = 0;
    for (int i = lo; i < hi; ++i) s += cnt[i];
    part[t] = s;
    __syncthreads();
    for (int o = 1; o < 1024; o <<= 1) {
        int v = (t >= o) ? part[t - o] : 0;
        __syncthreads();
        part[t] += v;
        __syncthreads();
    }
    int base = (t == 0) ? 0 : part[t - 1];
    for (int i = lo; i < hi; ++i) {
        offs[i] = base;
        cur[i]  = base;
        base += cnt[i];
    }
    if (t == 1023) offs[NN] = base;
}

__global__ void k_scatter4(const int* __restrict__ s0, const int* __restrict__ d0,
                           const int* __restrict__ s1, const int* __restrict__ d1,
                           const int* __restrict__ s2, const int* __restrict__ d2,
                           const int* __restrict__ s3, const int* __restrict__ d3,
                           int* __restrict__ cur, int* __restrict__ ssrc) {
    int e = blockIdx.x * 256 + threadIdx.x;
    int r = blockIdx.y;
    const int* src = r == 0 ? s0 : r == 1 ? s1 : r == 2 ? s2 : s3;
    const int* dst = r == 0 ? d0 : r == 1 ? d1 : r == 2 ? d2 : d3;
    if (e < NE) {
        int v = dst[e];
        int pos = atomicAdd(&cur[r * NN + v], 1);
        ssrc[r * NE + pos] = src[e];
    }
}

// EmbeddingBag(sum, per_sample_weights) + bias + relu. Warp per node.
__global__ void k_embed(const int* __restrict__ idx, const int* __restrict__ offs,
                        const float* __restrict__ wts, const float* __restrict__ table,
                        const float* __restrict__ bias, float* __restrict__ out) {
    int n = blockIdx.x * 8 + (threadIdx.x >> 5);
    if (n >= NN) return;
    int lane = threadIdx.x & 31;
    int s = offs[n], e = offs[n + 1];
    float4 acc = make_float4(0.f, 0.f, 0.f, 0.f);
    for (int base = s; base < e; base += 32) {
        int j = base + lane;
        int id = (j < e) ? idx[j] : 0;
        float w = (j < e) ? wts[j] : 0.f;
        int cnt = min(32, e - base);
#pragma unroll 2
        for (int t = 0; t < cnt; ++t) {
            int   uj = __shfl_sync(0xffffffffu, id, t);
            float wj = __shfl_sync(0xffffffffu, w,  t);
            float4 tv = *(const float4*)&table[(size_t)uj * HD + lane * 4];
            acc.x = fmaf(tv.x, wj, acc.x);
            acc.y = fmaf(tv.y, wj, acc.y);
            acc.z = fmaf(tv.z, wj, acc.z);
            acc.w = fmaf(tv.w, wj, acc.w);
        }
    }
    float4 b4 = *(const float4*)&bias[lane * 4];
    float4 r;
    r.x = fmaxf(acc.x + b4.x, 0.f);
    r.y = fmaxf(acc.y + b4.y, 0.f);
    r.z = fmaxf(acc.z + b4.z, 0.f);
    r.w = fmaxf(acc.w + b4.w, 0.f);
    *(float4*)&out[(size_t)n * HD + lane * 4] = r;
}

// C[n,OUT] = X[n,128] @ W[128,OUT] + Bias, optionally fused LayerNorm(128)+ReLU.
__global__ __launch_bounds__(256, 2)
void k_gemm(const float* __restrict__ X, const float* __restrict__ W,
            const float* __restrict__ Bias, const float* __restrict__ lng,
            const float* __restrict__ lnb, float* __restrict__ C,
            int n, int OUT, int do_ln) {
    __shared__ float xs[32][132];
    __shared__ float ws[32][132];
    int row0 = blockIdx.x * 128, col0 = blockIdx.y * 128;
    int tid = threadIdx.x;
    int tx = tid & 15, ty = tid >> 4;
    u64 acc2[8][4] = {};
    for (int kb = 0; kb < 128; kb += 32) {
#pragma unroll
        for (int it = 0; it < 4; ++it) {
            int idx = it * 256 + tid;
            int m = idx >> 3, kq = (idx & 7) * 4;
            int row = row0 + m;
            float4 v = (row < n) ? *(const float4*)&X[(size_t)row * 128 + kb + kq]
                                 : make_float4(0.f, 0.f, 0.f, 0.f);
            xs[kq + 0][m] = v.x; xs[kq + 1][m] = v.y;
            xs[kq + 2][m] = v.z; xs[kq + 3][m] = v.w;
        }
#pragma unroll
        for (int it = 0; it < 4; ++it) {
            int idx = it * 256 + tid;
            int k = idx >> 5, cq = (idx & 31) * 4;
            *(float4*)&ws[k][cq] = *(const float4*)&W[(size_t)(kb + k) * OUT + col0 + cq];
        }
        __syncthreads();
#pragma unroll
        for (int k = 0; k < 32; ++k) {
            float4 a0 = *(const float4*)&xs[k][ty * 4];
            float4 a1 = *(const float4*)&xs[k][64 + ty * 4];
            const u64* bp0 = (const u64*)&ws[k][tx * 4];
            const u64* bp1 = (const u64*)&ws[k][64 + tx * 4];
            u64 b01 = bp0[0], b23 = bp0[1];
            u64 b45 = bp1[0], b67 = bp1[1];
            float av[8] = {a0.x, a0.y, a0.z, a0.w, a1.x, a1.y, a1.z, a1.w};
#pragma unroll
            for (int i = 0; i < 8; ++i) {
                u64 aa = pack2(av[i], av[i]);
                acc2[i][0] = fma2(aa, b01, acc2[i][0]);
                acc2[i][1] = fma2(aa, b23, acc2[i][1]);
                acc2[i][2] = fma2(aa, b45, acc2[i][2]);
                acc2[i][3] = fma2(aa, b67, acc2[i][3]);
            }
        }
        __syncthreads();
    }
    float acc[8][8];
#pragma unroll
    for (int i = 0; i < 8; ++i)
#pragma unroll
        for (int q = 0; q < 4; ++q)
            unpack2(acc2[i][q], acc[i][q * 2], acc[i][q * 2 + 1]);

    float pb[8];
#pragma unroll
    for (int j = 0; j < 8; ++j) {
        int col = col0 + (j < 4 ? tx * 4 + j : 64 + tx * 4 + j - 4);
        pb[j] = Bias[col];
    }
#pragma unroll
    for (int i = 0; i < 8; ++i)
#pragma unroll
        for (int j = 0; j < 8; ++j) acc[i][j] += pb[j];

    if (do_ln) {
        float gv[8], b2[8];
#pragma unroll
        for (int j = 0; j < 8; ++j) {
            int col = (j < 4 ? tx * 4 + j : 64 + tx * 4 + j - 4);
            gv[j] = lng[col]; b2[j] = lnb[col];
        }
#pragma unroll
        for (int i = 0; i < 8; ++i) {
            float s = 0.f;
#pragma unroll
            for (int j = 0; j < 8; ++j) s += acc[i][j];
#pragma unroll
            for (int o = 1; o < 16; o <<= 1) s += __shfl_xor_sync(0xffffffffu, s, o);
            float mu = s * (1.f / 128.f);
            float q = 0.f;
#pragma unroll
            for (int j = 0; j < 8; ++j) { float d = acc[i][j] - mu; q += d * d; }
#pragma unroll
            for (int o = 1; o < 16; o <<= 1) q += __shfl_xor_sync(0xffffffffu, q, o);
            float rs = rsqrtf(q * (1.f / 128.f) + LN_EPS);
#pragma unroll
            for (int j = 0; j < 8; ++j)
                acc[i][j] = fmaxf((acc[i][j] - mu) * rs * gv[j] + b2[j], 0.f);
        }
    }
#pragma unroll
    for (int i = 0; i < 8; ++i) {
        int row = row0 + (i < 4 ? ty * 4 + i : 64 + ty * 4 + i - 4);
        if (row < n) {
            float4 o0 = make_float4(acc[i][0], acc[i][1], acc[i][2], acc[i][3]);
            float4 o1 = make_float4(acc[i][4], acc[i][5], acc[i][6], acc[i][7]);
            *(float4*)&C[(size_t)row * OUT + col0 + tx * 4]      = o0;
            *(float4*)&C[(size_t)row * OUT + col0 + 64 + tx * 4] = o1;
        }
    }
}

// ---------------- fused per-destination prop kernel ----------------
// Single-pass online-softmax GAT + label prop, f32x2-packed math.
// Score uses lrelu(z) = 0.6z + 0.4|z| with pre-scaled attn vectors.
__global__ void k_prop(const float* __restrict__ f, const float* __restrict__ x,
                       const float* __restrict__ yin, const float* __restrict__ attn,
                       const int* __restrict__ offp, const int* __restrict__ sp,
                       const int* __restrict__ offs2, const int* __restrict__ ss,
                       const void* __restrict__ flag,
                       float* __restrict__ hout, float* __restrict__ yout) {
    int v = blockIdx.x * 8 + (threadIdx.x >> 5);
    if (v >= NN) return;
    int lane = threadIdx.x & 31;

    float4 at = *(const float4*)&attn[lane * 4];
    u64 at06_0 = pack2(0.6f * at.x, 0.6f * at.y);
    u64 at06_1 = pack2(0.6f * at.z, 0.6f * at.w);
    u64 at04_0 = pack2(0.4f * at.x, 0.4f * at.y);
    u64 at04_1 = pack2(0.4f * at.z, 0.4f * at.w);
    ulonglong2 fv2 = *(const ulonglong2*)&f[(size_t)v * HD + lane * 4];

    float4 tf  = make_float4(0.f, 0.f, 0.f, 0.f);
    float4 ty0 = make_float4(0.f, 0.f, 0.f, 0.f);
    float4 ty1 = make_float4(0.f, 0.f, 0.f, 0.f);

#pragma unroll
    for (int rel = 0; rel < 2; ++rel) {
        const int* off  = rel ? offs2 : offp;
        const int* ssrc = rel ? ss    : sp;
        int lo = off[v], hi = off[v + 1];

        float m   = -__int_as_float(0x7f800000);
        float den = 0.f;
        u64 af0 = 0, af1 = 0, a00 = 0, a01 = 0, a10 = 0, a11 = 0;

        for (int base = lo; base < hi; base += 32) {
            int j = base + lane;
            int myu = (j < hi) ? __ldg(&ssrc[j]) : 0;
            int cnt = min(32, hi - base);
#pragma unroll 2
            for (int t = 0; t < cnt; ++t) {
                int u = __shfl_sync(0xffffffffu, myu, t);
                ulonglong2 fu = *(const ulonglong2*)&f[(size_t)u * HD + lane * 4];
                ulonglong2 y0 = *(const ulonglong2*)&yin[(size_t)u * OD + lane * 4];
                ulonglong2 y1 = *(const ulonglong2*)&yin[(size_t)u * OD + 128 + lane * 4];
                u64 z0 = add2(fu.x, fv2.x);
                u64 z1 = add2(fu.y, fv2.y);
                u64 p2 = mul2(z0, at06_0);
                p2 = fma2(abs2(z0), at04_0, p2);
                p2 = fma2(z1, at06_1, p2);
                p2 = fma2(abs2(z1), at04_1, p2);
                float px, py;
                unpack2(p2, px, py);
                float p = px + py;
#pragma unroll
                for (int o = 16; o; o >>= 1) p += __shfl_xor_sync(0xffffffffu, p, o);
                if (p > m) {
                    float r = __expf(m - p);   // 0 on first edge (m = -inf)
                    den *= r;
                    u64 r2 = pack2(r, r);
                    af0 = mul2(af0, r2); af1 = mul2(af1, r2);
                    a00 = mul2(a00, r2); a01 = mul2(a01, r2);
                    a10 = mul2(a10, r2); a11 = mul2(a11, r2);
                    m = p;
                }
                float w = __expf(p - m);
                den += w;
                u64 w2 = pack2(w, w);
                af0 = fma2(fu.x, w2, af0); af1 = fma2(fu.y, w2, af1);
                a00 = fma2(y0.x, w2, a00); a01 = fma2(y0.y, w2, a01);
                a10 = fma2(y1.x, w2, a10); a11 = fma2(y1.y, w2, a11);
            }
        }
        float rden = (den > 0.f) ? 1.f / den : 0.f;
        float e0, e1;
        unpack2(af0, e0, e1); tf.x  = fmaf(e0, rden, tf.x);  tf.y  = fmaf(e1, rden, tf.y);
        unpack2(af1, e0, e1); tf.z  = fmaf(e0, rden, tf.z);  tf.w  = fmaf(e1, rden, tf.w);
        unpack2(a00, e0, e1); ty0.x = fmaf(e0, rden, ty0.x); ty0.y = fmaf(e1, rden, ty0.y);
        unpack2(a01, e0, e1); ty0.z = fmaf(e0, rden, ty0.z); ty0.w = fmaf(e1, rden, ty0.w);
        unpack2(a10, e0, e1); ty1.x = fmaf(e0, rden, ty1.x); ty1.y = fmaf(e1, rden, ty1.y);
        unpack2(a11, e0, e1); ty1.z = fmaf(e0, rden, ty1.z); ty1.w = fmaf(e1, rden, ty1.w);
    }

    // h epilogue: elu(agg_p + agg_s + 2*x)
    float4 xv = *(const float4*)&x[(size_t)v * HD + lane * 4];
    float4 h;
    h.x = tf.x + 2.f * xv.x; h.x = h.x > 0.f ? h.x : expm1f(h.x);
    h.y = tf.y + 2.f * xv.y; h.y = h.y > 0.f ? h.y : expm1f(h.y);
    h.z = tf.z + 2.f * xv.z; h.z = h.z > 0.f ? h.z : expm1f(h.z);
    h.w = tf.w + 2.f * xv.w; h.w = h.w > 0.f ? h.w : expm1f(h.w);
    *(float4*)&hout[(size_t)v * HD + lane * 4] = h;

    // y epilogue: normalize or copy per flag
    float q = ty0.x * ty0.x + ty0.y * ty0.y + ty0.z * ty0.z + ty0.w * ty0.w
            + ty1.x * ty1.x + ty1.y * ty1.y + ty1.z * ty1.z + ty1.w * ty1.w;
#pragma unroll
    for (int o = 16; o; o >>= 1) q += __shfl_xor_sync(0xffffffffu, q, o);
    float inv = 1.f / fmaxf(sqrtf(q), 1e-12f);
    bool fl;
    if (g_flagIsInt) fl = ((const int*)flag)[v] != 0;
    else             fl = ((const unsigned char*)flag)[v] != 0;
    size_t base = (size_t)v * OD + lane * 4;
    float4 r0, r1;
    if (fl) {
        r0 = *(const float4*)&yin[base];
        r1 = *(const float4*)&yin[base + 128];
    } else {
        r0 = make_float4(ty0.x * inv, ty0.y * inv, ty0.z * inv, ty0.w * inv);
        r1 = make_float4(ty1.x * inv, ty1.y * inv, ty1.z * inv, ty1.w * inv);
    }
    *(float4*)&yout[base]       = r0;
    *(float4*)&yout[base + 128] = r1;
}

// ---------------- host orchestration ----------------
extern "C" void kernel_launch(void* const* d_in, const int* in_sizes, int n_in,
                              void* d_out, int out_size) {
    const int*   emb_indices = (const int*)  d_in[0];
    const int*   emb_offsets = (const int*)  d_in[1];
    const float* emb_weights = (const float*)d_in[2];
    const float* y           = (const float*)d_in[3];
    const void*  flag        = d_in[4];
    const int* src_p1 = (const int*)d_in[5];
    const int* dst_p1 = (const int*)d_in[6];
    const int* src_s1 = (const int*)d_in[7];
    const int* dst_s1 = (const int*)d_in[8];
    const int* src_p2 = (const int*)d_in[9];
    const int* dst_p2 = (const int*)d_in[10];
    const int* src_s2 = (const int*)d_in[11];
    const int* dst_s2 = (const int*)d_in[12];
    const float* embed_W = (const float*)d_in[13];
    const float* embed_b = (const float*)d_in[14];
    const float* mlp_W1  = (const float*)d_in[15];
    const float* mlp_b1  = (const float*)d_in[16];
    const float* ln1_g   = (const float*)d_in[17];
    const float* ln1_b   = (const float*)d_in[18];
    const float* mlp_W2  = (const float*)d_in[19];
    const float* mlp_b2  = (const float*)d_in[20];
    const float* ln2_g   = (const float*)d_in[21];
    const float* ln2_b   = (const float*)d_in[22];
    const float* Wsrc1   = (const float*)d_in[23];
    const float* bsrc1   = (const float*)d_in[24];
    const float* attn1   = (const float*)d_in[25];
    const float* Wsrc2   = (const float*)d_in[26];
    const float* bsrc2   = (const float*)d_in[27];
    const float* attn2   = (const float*)d_in[28];
    const float* out_W   = (const float*)d_in[29];
    const float* out_b   = (const float*)d_in[30];

    float *hA, *hB, *f, *yA;
    int *off, *ssrc, *cnt, *cur;
    cudaGetSymbolAddress((void**)&hA,   g_hA);
    cudaGetSymbolAddress((void**)&hB,   g_hB);
    cudaGetSymbolAddress((void**)&f,    g_f);
    cudaGetSymbolAddress((void**)&yA,   g_yA);
    cudaGetSymbolAddress((void**)&off,  g_off);
    cudaGetSymbolAddress((void**)&ssrc, g_ssrc);
    cudaGetSymbolAddress((void**)&cnt,  g_cnt);
    cudaGetSymbolAddress((void**)&cur,  g_cur);

    float* logits = (float*)d_out;
    float* yh_out = (float*)d_out + (size_t)NN * OD;

    // Side stream for the CSR build (independent of embed+MLP); capture-legal
    // fork/join via events. Handles are leaked intentionally (few calls total;
    // destroying during capture is unsafe; no device memory involved).
    cudaStream_t s2;
    cudaEvent_t ev0, ev1;
    cudaStreamCreateWithFlags(&s2, cudaStreamNonBlocking);
    cudaEventCreateWithFlags(&ev0, cudaEventDisableTiming);
    cudaEventCreateWithFlags(&ev1, cudaEventDisableTiming);

    cudaEventRecord(ev0, 0);

    // ---- main branch: EmbeddingBag + MLP (LN fused) + f-GEMM for prop1 ----
    k_embed<<<(NN + 7) / 8, 256>>>(emb_indices, emb_offsets, emb_weights, embed_W, embed_b, hA);
    dim3 g1((NN + 127) / 128, 1);
    k_gemm<<<g1, 256>>>(hA, mlp_W1, mlp_b1, ln1_g, ln1_b, hB, NN, 128, 1);
    k_gemm<<<g1, 256>>>(hB, mlp_W2, mlp_b2, ln2_g, ln2_b, hA, NN, 128, 1);
    k_gemm<<<g1, 256>>>(hA, Wsrc1, bsrc1, nullptr, nullptr, f, NN, 128, 0);

    // ---- side branch: flag detect + CSR sorts for the 4 relations ----
    cudaStreamWaitEvent(s2, ev0, 0);
    k_detect_flag<<<1, 256, 0, s2>>>((const unsigned char*)flag);
    cudaMemsetAsync(cnt, 0, sizeof(int) * 4 * NN, s2);
    dim3 ge((NE + 255) / 256, 4);
    k_hist4<<<ge, 256, 0, s2>>>(dst_p1, dst_s1, dst_p2, dst_s2, cnt);
    k_scan4<<<4, 1024, 0, s2>>>(cnt, off, cur);
    k_scatter4<<<ge, 256, 0, s2>>>(src_p1, dst_p1, src_s1, dst_s1,
                                   src_p2, dst_p2, src_s2, dst_s2, cur, ssrc);
    cudaEventRecord(ev1, s2);

    // ---- join, then props ----
    cudaStreamWaitEvent(0, ev1, 0);
    k_prop<<<(NN + 7) / 8, 256>>>(f, hA, y, attn1,
                                  off + 0 * (NN + 1), ssrc + 0 * NE,
                                  off + 1 * (NN + 1), ssrc + 1 * NE,
                                  flag, hB, yA);

    k_gemm<<<g1, 256>>>(hB, Wsrc2, bsrc2, nullptr, nullptr, f, NN, 128, 0);
    k_prop<<<(NN + 7) / 8, 256>>>(f, hB, yA, attn2,
                                  off + 2 * (NN + 1), ssrc + 2 * NE,
                                  off + 3 * (NN + 1), ssrc + 3 * NE,
                                  flag, hA, yh_out);

    // ---- logits = h @ out_W + out_b ----
    dim3 g2((NN + 127) / 128, 2);
    k_gemm<<<g2, 256>>>(hA, out_W, out_b, nullptr, nullptr, logits, NN, 256, 0);
}

// round 10
// speedup vs baseline: 3.0548x; 1.0498x over previous
#include <cuda_runtime.h>
#include <math.h>

#define NN 50000
#define HD 128
#define OD 256
#define NE 800000
#define LN_EPS 1e-5f

typedef unsigned long long u64;

// ---------------- scratch (static device globals; no allocation) ----------------
__device__ float g_hA[NN * HD];
__device__ float g_hB[NN * HD];
__device__ float g_f [NN * HD];
__device__ float g_yA [NN * OD];
__device__ int   g_off [4][NN + 1];
__device__ int   g_ssrc[4][NE];
__device__ int   g_cnt[4][NN];
__device__ int   g_cur[4][NN];
__device__ int   g_flagIsInt;

// ---------------- helpers ----------------
__device__ __forceinline__ u64 pack2(float lo, float hi) {
    u64 r;
    asm("mov.b64 %0, {%1, %2};" : "=l"(r) : "f"(lo), "f"(hi));
    return r;
}
__device__ __forceinline__ void unpack2(u64 v, float& lo, float& hi) {
    asm("mov.b64 {%0, %1}, %2;" : "=f"(lo), "=f"(hi) : "l"(v));
}
__device__ __forceinline__ u64 fma2(u64 a, u64 b, u64 c) {
    u64 d;
    asm("fma.rn.f32x2 %0, %1, %2, %3;" : "=l"(d) : "l"(a), "l"(b), "l"(c));
    return d;
}
__device__ __forceinline__ u64 mul2(u64 a, u64 b) {
    u64 d;
    asm("mul.rn.f32x2 %0, %1, %2;" : "=l"(d) : "l"(a), "l"(b));
    return d;
}
__device__ __forceinline__ u64 add2(u64 a, u64 b) {
    u64 d;
    asm("add.rn.f32x2 %0, %1, %2;" : "=l"(d) : "l"(a), "l"(b));
    return d;
}
__device__ __forceinline__ u64 abs2(u64 a) {
    return a & 0x7FFFFFFF7FFFFFFFULL;
}

// ---------------- kernels ----------------

// Detect flag buffer layout: int32 (bytes 1..3 of each word are 0) vs uint8.
__global__ void k_detect_flag(const unsigned char* __restrict__ flag) {
    __shared__ int cnt;
    if (threadIdx.x == 0) cnt = 0;
    __syncthreads();
    int local = 0;
    for (int i = threadIdx.x; i < 4000; i += 256)
        if ((i & 3) != 0 && flag[i] != 0) local = 1;
    if (local) atomicOr(&cnt, 1);
    __syncthreads();
    if (threadIdx.x == 0) g_flagIsInt = (cnt == 0) ? 1 : 0;
}

// -------- counting sort by dst (all 4 relations in one grid via blockIdx.y) --------
__global__ void k_hist4(const int* __restrict__ d0, const int* __restrict__ d1,
                        const int* __restrict__ d2, const int* __restrict__ d3,
                        int* __restrict__ cnt) {
    int e = blockIdx.x * 256 + threadIdx.x;
    int r = blockIdx.y;
    const int* dst = r == 0 ? d0 : r == 1 ? d1 : r == 2 ? d2 : d3;
    if (e < NE) atomicAdd(&cnt[r * NN + dst[e]], 1);
}

// 4 blocks, one relation each: exclusive scan -> offs[NN+1], cur[NN]
__global__ void k_scan4(const int* __restrict__ cntAll, int* __restrict__ offsAll,
                        int* __restrict__ curAll) {
    __shared__ int part[1024];
    const int CH = (NN + 1023) / 1024;
    int r = blockIdx.x;
    const int* cnt = cntAll + r * NN;
    int* offs = offsAll + r * (NN + 1);
    int* cur  = curAll  + r * NN;
    int t = threadIdx.x;
    int lo = t * CH, hi = min(lo + CH, NN);
    int s = 0;
    for (int i = lo; i < hi; ++i) s += cnt[i];
    part[t] = s;
    __syncthreads();
    for (int o = 1; o < 1024; o <<= 1) {
        int v = (t >= o) ? part[t - o] : 0;
        __syncthreads();
        part[t] += v;
        __syncthreads();
    }
    int base = (t == 0) ? 0 : part[t - 1];
    for (int i = lo; i < hi; ++i) {
        offs[i] = base;
        cur[i]  = base;
        base += cnt[i];
    }
    if (t == 1023) offs[NN] = base;
}

__global__ void k_scatter4(const int* __restrict__ s0, const int* __restrict__ d0,
                           const int* __restrict__ s1, const int* __restrict__ d1,
                           const int* __restrict__ s2, const int* __restrict__ d2,
                           const int* __restrict__ s3, const int* __restrict__ d3,
                           int* __restrict__ cur, int* __restrict__ ssrc) {
    int e = blockIdx.x * 256 + threadIdx.x;
    int r = blockIdx.y;
    const int* src = r == 0 ? s0 : r == 1 ? s1 : r == 2 ? s2 : s3;
    const int* dst = r == 0 ? d0 : r == 1 ? d1 : r == 2 ? d2 : d3;
    if (e < NE) {
        int v = dst[e];
        int pos = atomicAdd(&cur[r * NN + v], 1);
        ssrc[r * NE + pos] = src[e];
    }
}

// EmbeddingBag(sum, per_sample_weights) + bias + relu. Warp per node.
__global__ void k_embed(const int* __restrict__ idx, const int* __restrict__ offs,
                        const float* __restrict__ wts, const float* __restrict__ table,
                        const float* __restrict__ bias, float* __restrict__ out) {
    int n = blockIdx.x * 8 + (threadIdx.x >> 5);
    if (n >= NN) return;
    int lane = threadIdx.x & 31;
    int s = offs[n], e = offs[n + 1];
    float4 acc = make_float4(0.f, 0.f, 0.f, 0.f);
    for (int base = s; base < e; base += 32) {
        int j = base + lane;
        int id = (j < e) ? idx[j] : 0;
        float w = (j < e) ? wts[j] : 0.f;
        int cnt = min(32, e - base);
#pragma unroll 2
        for (int t = 0; t < cnt; ++t) {
            int   uj = __shfl_sync(0xffffffffu, id, t);
            float wj = __shfl_sync(0xffffffffu, w,  t);
            float4 tv = *(const float4*)&table[(size_t)uj * HD + lane * 4];
            acc.x = fmaf(tv.x, wj, acc.x);
            acc.y = fmaf(tv.y, wj, acc.y);
            acc.z = fmaf(tv.z, wj, acc.z);
            acc.w = fmaf(tv.w, wj, acc.w);
        }
    }
    float4 b4 = *(const float4*)&bias[lane * 4];
    float4 r;
    r.x = fmaxf(acc.x + b4.x, 0.f);
    r.y = fmaxf(acc.y + b4.y, 0.f);
    r.z = fmaxf(acc.z + b4.z, 0.f);
    r.w = fmaxf(acc.w + b4.w, 0.f);
    *(float4*)&out[(size_t)n * HD + lane * 4] = r;
}

// C[n,OUT] = X[n,128] @ W[128,OUT] + Bias, optionally fused LayerNorm(128)+ReLU.
// 128x128 tile, 256 threads, FFMA2 inner loop, DOUBLE-BUFFERED smem stages:
// stage k+1 is loaded global->regs during stage k's compute, one sync/stage.
__global__ __launch_bounds__(256, 2)
void k_gemm(const float* __restrict__ X, const float* __restrict__ W,
            const float* __restrict__ Bias, const float* __restrict__ lng,
            const float* __restrict__ lnb, float* __restrict__ C,
            int n, int OUT, int do_ln) {
    __shared__ float xs[2][32][132];
    __shared__ float ws[2][32][132];
    int row0 = blockIdx.x * 128, col0 = blockIdx.y * 128;
    int tid = threadIdx.x;
    int tx = tid & 15, ty = tid >> 4;

    // per-thread load coordinates (constant across stages)
    int xm = tid >> 1, xk = (tid & 1) * 16;           // X: 2 float4 rows? see below
    int wk0 = tid >> 5, wc = (tid & 31) * 4;          // W: 4 k-rows per thread

    // X stage: 128 rows x 32 k = 16 float4/thread? No: 4096 floats /256 thr = 16 floats
    //   thread loads 4 float4: rows (tid>>1), k quarter (tid&1)*16 .. +12 -> 4x float4
    // W stage: 32 k x 128 cols = 4096 floats: thread loads rows wk0+{0,8,16,24}, col wc
    float4 xr[4], wr[4];
    int buf = 0;

    // prologue: load stage 0
    {
        int kb = 0;
#pragma unroll
        for (int q = 0; q < 4; ++q) {
            int row = row0 + xm;
            xr[q] = (row < n) ? *(const float4*)&X[(size_t)row * 128 + kb + xk + q * 4]
                              : make_float4(0.f, 0.f, 0.f, 0.f);
        }
#pragma unroll
        for (int q = 0; q < 4; ++q)
            wr[q] = *(const float4*)&W[(size_t)(kb + wk0 + q * 8) * OUT + col0 + wc];
#pragma unroll
        for (int q = 0; q < 4; ++q) {
            xs[0][xk + q * 4 + 0][xm] = xr[q].x;
            xs[0][xk + q * 4 + 1][xm] = xr[q].y;
            xs[0][xk + q * 4 + 2][xm] = xr[q].z;
            xs[0][xk + q * 4 + 3][xm] = xr[q].w;
            *(float4*)&ws[0][wk0 + q * 8][wc] = wr[q];
        }
    }
    __syncthreads();

    u64 acc2[8][4] = {};
#pragma unroll
    for (int kb = 0; kb < 128; kb += 32) {
        // issue loads for next stage (global -> regs), overlapping compute
        if (kb + 32 < 128) {
            int kn = kb + 32;
#pragma unroll
            for (int q = 0; q < 4; ++q) {
                int row = row0 + xm;
                xr[q] = (row < n) ? *(const float4*)&X[(size_t)row * 128 + kn + xk + q * 4]
                                  : make_float4(0.f, 0.f, 0.f, 0.f);
            }
#pragma unroll
            for (int q = 0; q < 4; ++q)
                wr[q] = *(const float4*)&W[(size_t)(kn + wk0 + q * 8) * OUT + col0 + wc];
        }
        // compute current stage
#pragma unroll
        for (int k = 0; k < 32; ++k) {
            float4 a0 = *(const float4*)&xs[buf][k][ty * 4];
            float4 a1 = *(const float4*)&xs[buf][k][64 + ty * 4];
            const u64* bp0 = (const u64*)&ws[buf][k][tx * 4];
            const u64* bp1 = (const u64*)&ws[buf][k][64 + tx * 4];
            u64 b01 = bp0[0], b23 = bp0[1];
            u64 b45 = bp1[0], b67 = bp1[1];
            float av[8] = {a0.x, a0.y, a0.z, a0.w, a1.x, a1.y, a1.z, a1.w};
#pragma unroll
            for (int i = 0; i < 8; ++i) {
                u64 aa = pack2(av[i], av[i]);
                acc2[i][0] = fma2(aa, b01, acc2[i][0]);
                acc2[i][1] = fma2(aa, b23, acc2[i][1]);
                acc2[i][2] = fma2(aa, b45, acc2[i][2]);
                acc2[i][3] = fma2(aa, b67, acc2[i][3]);
            }
        }
        // store next stage to smem and flip
        if (kb + 32 < 128) {
            int nb = buf ^ 1;
#pragma unroll
            for (int q = 0; q < 4; ++q) {
                xs[nb][xk + q * 4 + 0][xm] = xr[q].x;
                xs[nb][xk + q * 4 + 1][xm] = xr[q].y;
                xs[nb][xk + q * 4 + 2][xm] = xr[q].z;
                xs[nb][xk + q * 4 + 3][xm] = xr[q].w;
                *(float4*)&ws[nb][wk0 + q * 8][wc] = wr[q];
            }
            __syncthreads();
            buf = nb;
        }
    }

    float acc[8][8];
#pragma unroll
    for (int i = 0; i < 8; ++i)
#pragma unroll
        for (int q = 0; q < 4; ++q)
            unpack2(acc2[i][q], acc[i][q * 2], acc[i][q * 2 + 1]);

    float pb[8];
#pragma unroll
    for (int j = 0; j < 8; ++j) {
        int col = col0 + (j < 4 ? tx * 4 + j : 64 + tx * 4 + j - 4);
        pb[j] = Bias[col];
    }
#pragma unroll
    for (int i = 0; i < 8; ++i)
#pragma unroll
        for (int j = 0; j < 8; ++j) acc[i][j] += pb[j];

    if (do_ln) {
        float gv[8], b2[8];
#pragma unroll
        for (int j = 0; j < 8; ++j) {
            int col = (j < 4 ? tx * 4 + j : 64 + tx * 4 + j - 4);
            gv[j] = lng[col]; b2[j] = lnb[col];
        }
#pragma unroll
        for (int i = 0; i < 8; ++i) {
            float s = 0.f;
#pragma unroll
            for (int j = 0; j < 8; ++j) s += acc[i][j];
#pragma unroll
            for (int o = 1; o < 16; o <<= 1) s += __shfl_xor_sync(0xffffffffu, s, o);
            float mu = s * (1.f / 128.f);
            float q = 0.f;
#pragma unroll
            for (int j = 0; j < 8; ++j) { float d = acc[i][j] - mu; q += d * d; }
#pragma unroll
            for (int o = 1; o < 16; o <<= 1) q += __shfl_xor_sync(0xffffffffu, q, o);
            float rs = rsqrtf(q * (1.f / 128.f) + LN_EPS);
#pragma unroll
            for (int j = 0; j < 8; ++j)
                acc[i][j] = fmaxf((acc[i][j] - mu) * rs * gv[j] + b2[j], 0.f);
        }
    }
#pragma unroll
    for (int i = 0; i < 8; ++i) {
        int row = row0 + (i < 4 ? ty * 4 + i : 64 + ty * 4 + i - 4);
        if (row < n) {
            float4 o0 = make_float4(acc[i][0], acc[i][1], acc[i][2], acc[i][3]);
            float4 o1 = make_float4(acc[i][4], acc[i][5], acc[i][6], acc[i][7]);
            *(float4*)&C[(size_t)row * OUT + col0 + tx * 4]      = o0;
            *(float4*)&C[(size_t)row * OUT + col0 + 64 + tx * 4] = o1;
        }
    }
}

// ---------------- fused per-destination prop kernel ----------------
// Single-pass online-softmax GAT + label prop, f32x2-packed math.
__global__ void k_prop(const float* __restrict__ f, const float* __restrict__ x,
                       const float* __restrict__ yin, const float* __restrict__ attn,
                       const int* __restrict__ offp, const int* __restrict__ sp,
                       const int* __restrict__ offs2, const int* __restrict__ ss,
                       const void* __restrict__ flag,
                       float* __restrict__ hout, float* __restrict__ yout) {
    int v = blockIdx.x * 8 + (threadIdx.x >> 5);
    if (v >= NN) return;
    int lane = threadIdx.x & 31;

    float4 at = *(const float4*)&attn[lane * 4];
    u64 at06_0 = pack2(0.6f * at.x, 0.6f * at.y);
    u64 at06_1 = pack2(0.6f * at.z, 0.6f * at.w);
    u64 at04_0 = pack2(0.4f * at.x, 0.4f * at.y);
    u64 at04_1 = pack2(0.4f * at.z, 0.4f * at.w);
    ulonglong2 fv2 = *(const ulonglong2*)&f[(size_t)v * HD + lane * 4];

    float4 tf  = make_float4(0.f, 0.f, 0.f, 0.f);
    float4 ty0 = make_float4(0.f, 0.f, 0.f, 0.f);
    float4 ty1 = make_float4(0.f, 0.f, 0.f, 0.f);

#pragma unroll
    for (int rel = 0; rel < 2; ++rel) {
        const int* off  = rel ? offs2 : offp;
        const int* ssrc = rel ? ss    : sp;
        int lo = off[v], hi = off[v + 1];

        float m   = -__int_as_float(0x7f800000);
        float den = 0.f;
        u64 af0 = 0, af1 = 0, a00 = 0, a01 = 0, a10 = 0, a11 = 0;

        for (int base = lo; base < hi; base += 32) {
            int j = base + lane;
            int myu = (j < hi) ? __ldg(&ssrc[j]) : 0;
            int cnt = min(32, hi - base);
#pragma unroll 2
            for (int t = 0; t < cnt; ++t) {
                int u = __shfl_sync(0xffffffffu, myu, t);
                ulonglong2 fu = *(const ulonglong2*)&f[(size_t)u * HD + lane * 4];
                ulonglong2 y0 = *(const ulonglong2*)&yin[(size_t)u * OD + lane * 4];
                ulonglong2 y1 = *(const ulonglong2*)&yin[(size_t)u * OD + 128 + lane * 4];
                u64 z0 = add2(fu.x, fv2.x);
                u64 z1 = add2(fu.y, fv2.y);
                u64 p2 = mul2(z0, at06_0);
                p2 = fma2(abs2(z0), at04_0, p2);
                p2 = fma2(z1, at06_1, p2);
                p2 = fma2(abs2(z1), at04_1, p2);
                float px, py;
                unpack2(p2, px, py);
                float p = px + py;
#pragma unroll
                for (int o = 16; o; o >>= 1) p += __shfl_xor_sync(0xffffffffu, p, o);
                if (p > m) {
                    float r = __expf(m - p);   // 0 on first edge (m = -inf)
                    den *= r;
                    u64 r2 = pack2(r, r);
                    af0 = mul2(af0, r2); af1 = mul2(af1, r2);
                    a00 = mul2(a00, r2); a01 = mul2(a01, r2);
                    a10 = mul2(a10, r2); a11 = mul2(a11, r2);
                    m = p;
                }
                float w = __expf(p - m);
                den += w;
                u64 w2 = pack2(w, w);
                af0 = fma2(fu.x, w2, af0); af1 = fma2(fu.y, w2, af1);
                a00 = fma2(y0.x, w2, a00); a01 = fma2(y0.y, w2, a01);
                a10 = fma2(y1.x, w2, a10); a11 = fma2(y1.y, w2, a11);
            }
        }
        float rden = (den > 0.f) ? 1.f / den : 0.f;
        float e0, e1;
        unpack2(af0, e0, e1); tf.x  = fmaf(e0, rden, tf.x);  tf.y  = fmaf(e1, rden, tf.y);
        unpack2(af1, e0, e1); tf.z  = fmaf(e0, rden, tf.z);  tf.w  = fmaf(e1, rden, tf.w);
        unpack2(a00, e0, e1); ty0.x = fmaf(e0, rden, ty0.x); ty0.y = fmaf(e1, rden, ty0.y);
        unpack2(a01, e0, e1); ty0.z = fmaf(e0, rden, ty0.z); ty0.w = fmaf(e1, rden, ty0.w);
        unpack2(a10, e0, e1); ty1.x = fmaf(e0, rden, ty1.x); ty1.y = fmaf(e1, rden, ty1.y);
        unpack2(a11, e0, e1); ty1.z = fmaf(e0, rden, ty1.z); ty1.w = fmaf(e1, rden, ty1.w);
    }

    // h epilogue: elu(agg_p + agg_s + 2*x)
    float4 xv = *(const float4*)&x[(size_t)v * HD + lane * 4];
    float4 h;
    h.x = tf.x + 2.f * xv.x; h.x = h.x > 0.f ? h.x : expm1f(h.x);
    h.y = tf.y + 2.f * xv.y; h.y = h.y > 0.f ? h.y : expm1f(h.y);
    h.z = tf.z + 2.f * xv.z; h.z = h.z > 0.f ? h.z : expm1f(h.z);
    h.w = tf.w + 2.f * xv.w; h.w = h.w > 0.f ? h.w : expm1f(h.w);
    *(float4*)&hout[(size_t)v * HD + lane * 4] = h;

    // y epilogue: normalize or copy per flag
    float q = ty0.x * ty0.x + ty0.y * ty0.y + ty0.z * ty0.z + ty0.w * ty0.w
            + ty1.x * ty1.x + ty1.y * ty1.y + ty1.z * ty1.z + ty1.w * ty1.w;
#pragma unroll
    for (int o = 16; o; o >>= 1) q += __shfl_xor_sync(0xffffffffu, q, o);
    float inv = 1.f / fmaxf(sqrtf(q), 1e-12f);
    bool fl;
    if (g_flagIsInt) fl = ((const int*)flag)[v] != 0;
    else             fl = ((const unsigned char*)flag)[v] != 0;
    size_t base = (size_t)v * OD + lane * 4;
    float4 r0, r1;
    if (fl) {
        r0 = *(const float4*)&yin[base];
        r1 = *(const float4*)&yin[base + 128];
    } else {
        r0 = make_float4(ty0.x * inv, ty0.y * inv, ty0.z * inv, ty0.w * inv);
        r1 = make_float4(ty1.x * inv, ty1.y * inv, ty1.z * inv, ty1.w * inv);
    }
    *(float4*)&yout[base]       = r0;
    *(float4*)&yout[base + 128] = r1;
}

// ---------------- host orchestration ----------------
extern "C" void kernel_launch(void* const* d_in, const int* in_sizes, int n_in,
                              void* d_out, int out_size) {
    const int*   emb_indices = (const int*)  d_in[0];
    const int*   emb_offsets = (const int*)  d_in[1];
    const float* emb_weights = (const float*)d_in[2];
    const float* y           = (const float*)d_in[3];
    const void*  flag        = d_in[4];
    const int* src_p1 = (const int*)d_in[5];
    const int* dst_p1 = (const int*)d_in[6];
    const int* src_s1 = (const int*)d_in[7];
    const int* dst_s1 = (const int*)d_in[8];
    const int* src_p2 = (const int*)d_in[9];
    const int* dst_p2 = (const int*)d_in[10];
    const int* src_s2 = (const int*)d_in[11];
    const int* dst_s2 = (const int*)d_in[12];
    const float* embed_W = (const float*)d_in[13];
    const float* embed_b = (const float*)d_in[14];
    const float* mlp_W1  = (const float*)d_in[15];
    const float* mlp_b1  = (const float*)d_in[16];
    const float* ln1_g   = (const float*)d_in[17];
    const float* ln1_b   = (const float*)d_in[18];
    const float* mlp_W2  = (const float*)d_in[19];
    const float* mlp_b2  = (const float*)d_in[20];
    const float* ln2_g   = (const float*)d_in[21];
    const float* ln2_b   = (const float*)d_in[22];
    const float* Wsrc1   = (const float*)d_in[23];
    const float* bsrc1   = (const float*)d_in[24];
    const float* attn1   = (const float*)d_in[25];
    const float* Wsrc2   = (const float*)d_in[26];
    const float* bsrc2   = (const float*)d_in[27];
    const float* attn2   = (const float*)d_in[28];
    const float* out_W   = (const float*)d_in[29];
    const float* out_b   = (const float*)d_in[30];

    float *hA, *hB, *f, *yA;
    int *off, *ssrc, *cnt, *cur;
    cudaGetSymbolAddress((void**)&hA,   g_hA);
    cudaGetSymbolAddress((void**)&hB,   g_hB);
    cudaGetSymbolAddress((void**)&f,    g_f);
    cudaGetSymbolAddress((void**)&yA,   g_yA);
    cudaGetSymbolAddress((void**)&off,  g_off);
    cudaGetSymbolAddress((void**)&ssrc, g_ssrc);
    cudaGetSymbolAddress((void**)&cnt,  g_cnt);
    cudaGetSymbolAddress((void**)&cur,  g_cur);

    float* logits = (float*)d_out;
    float* yh_out = (float*)d_out + (size_t)NN * OD;

    // Side stream for the CSR build (independent of embed+MLP); capture-legal
    // fork/join via events. Handles are leaked intentionally (few calls total;
    // destroying during capture is unsafe; no device memory involved).
    cudaStream_t s2;
    cudaEvent_t ev0, ev1;
    cudaStreamCreateWithFlags(&s2, cudaStreamNonBlocking);
    cudaEventCreateWithFlags(&ev0, cudaEventDisableTiming);
    cudaEventCreateWithFlags(&ev1, cudaEventDisableTiming);

    cudaEventRecord(ev0, 0);

    // ---- main branch: EmbeddingBag + MLP (LN fused) + f-GEMM for prop1 ----
    k_embed<<<(NN + 7) / 8, 256>>>(emb_indices, emb_offsets, emb_weights, embed_W, embed_b, hA);
    dim3 g1((NN + 127) / 128, 1);
    k_gemm<<<g1, 256>>>(hA, mlp_W1, mlp_b1, ln1_g, ln1_b, hB, NN, 128, 1);
    k_gemm<<<g1, 256>>>(hB, mlp_W2, mlp_b2, ln2_g, ln2_b, hA, NN, 128, 1);
    k_gemm<<<g1, 256>>>(hA, Wsrc1, bsrc1, nullptr, nullptr, f, NN, 128, 0);

    // ---- side branch: flag detect + CSR sorts for the 4 relations ----
    cudaStreamWaitEvent(s2, ev0, 0);
    k_detect_flag<<<1, 256, 0, s2>>>((const unsigned char*)flag);
    cudaMemsetAsync(cnt, 0, sizeof(int) * 4 * NN, s2);
    dim3 ge((NE + 255) / 256, 4);
    k_hist4<<<ge, 256, 0, s2>>>(dst_p1, dst_s1, dst_p2, dst_s2, cnt);
    k_scan4<<<4, 1024, 0, s2>>>(cnt, off, cur);
    k_scatter4<<<ge, 256, 0, s2>>>(src_p1, dst_p1, src_s1, dst_s1,
                                   src_p2, dst_p2, src_s2, dst_s2, cur, ssrc);
    cudaEventRecord(ev1, s2);

    // ---- join, then props ----
    cudaStreamWaitEvent(0, ev1, 0);
    k_prop<<<(NN + 7) / 8, 256>>>(f, hA, y, attn1,
                                  off + 0 * (NN + 1), ssrc + 0 * NE,
                                  off + 1 * (NN + 1), ssrc + 1 * NE,
                                  flag, hB, yA);

    k_gemm<<<g1, 256>>>(hB, Wsrc2, bsrc2, nullptr, nullptr, f, NN, 128, 0);
    k_prop<<<(NN + 7) / 8, 256>>>(f, hB, yA, attn2,
                                  off + 2 * (NN + 1), ssrc + 2 * NE,
                                  off + 3 * (NN + 1), ssrc + 3 * NE,
                                  flag, hA, yh_out);

    // ---- logits = h @ out_W + out_b ----
    dim3 g2((NN + 127) / 128, 2);
    k_gemm<<<g2, 256>>>(hA, out_W, out_b, nullptr, nullptr, logits, NN, 256, 0);
}